// round 1
// baseline (speedup 1.0000x reference)
#include <cuda_runtime.h>
#include <cuda_bf16.h>
#include <math.h>

#define BB 2
#define TT 2048
#define DIM 1024
#define NH 16
#define HKV 4
#define HD 64
#define GRP 4

// ---------------- scratch (device globals, no allocation) ----------------
__device__ float g_wq[DIM * DIM];
__device__ float g_wk[HKV * HD * DIM];
__device__ float g_wv[HKV * HD * DIM];
__device__ float g_wp[DIM * DIM];
__device__ float g_q[BB * TT * NH * HD];
__device__ float g_k[BB * TT * HKV * HD];
__device__ float g_v[BB * TT * HKV * HD];
__device__ float g_y[BB * TT * NH * HD];
__device__ float g_yo[BB * TT * DIM];

// ---------------- fake_quant: per-row max-abs quantize ----------------
__global__ __launch_bounds__(256) void quant_kernel(const float* __restrict__ W,
                                                    float* __restrict__ Wq,
                                                    int cols, float halfv) {
    __shared__ float red[256];
    int r = blockIdx.x;
    const float* row = W + (size_t)r * cols;
    float m = 0.f;
    for (int c = threadIdx.x; c < cols; c += 256) m = fmaxf(m, fabsf(row[c]));
    red[threadIdx.x] = m;
    __syncthreads();
    for (int s = 128; s > 0; s >>= 1) {
        if (threadIdx.x < s) red[threadIdx.x] = fmaxf(red[threadIdx.x], red[threadIdx.x + s]);
        __syncthreads();
    }
    float wmax = fmaxf(red[0], 1e-5f);
    float sc = halfv / wmax, isc = wmax / halfv;
    float* orow = Wq + (size_t)r * cols;
    for (int c = threadIdx.x; c < cols; c += 256) {
        float q = rintf(row[c] * sc);          // round-half-even, matches jnp.round
        q = fminf(fmaxf(q, -halfv), halfv - 1.f);
        orow[c] = q * isc;
    }
}

// ---------------- SGEMM: C[M,N] = A[M,K] @ B[N,K]^T ----------------
// 128x128 tile, BK=8, 256 threads, 8x8 per thread
__global__ __launch_bounds__(256) void sgemm_nt(const float* __restrict__ A,
                                                const float* __restrict__ B,
                                                float* __restrict__ C,
                                                int M, int N, int K) {
    __shared__ float As[8][128];
    __shared__ float Bs[8][128];
    const int tid = threadIdx.x;
    const int tx = tid & 15, ty = tid >> 4;
    const int m0 = blockIdx.y * 128, n0 = blockIdx.x * 128;
    const int lr = tid >> 1;          // 0..127
    const int lk = (tid & 1) * 4;     // 0 or 4
    float acc[8][8];
#pragma unroll
    for (int i = 0; i < 8; i++)
#pragma unroll
        for (int j = 0; j < 8; j++) acc[i][j] = 0.f;

    for (int k0 = 0; k0 < K; k0 += 8) {
        float4 a4 = *reinterpret_cast<const float4*>(A + (size_t)(m0 + lr) * K + k0 + lk);
        float4 b4 = *reinterpret_cast<const float4*>(B + (size_t)(n0 + lr) * K + k0 + lk);
        As[lk + 0][lr] = a4.x; As[lk + 1][lr] = a4.y;
        As[lk + 2][lr] = a4.z; As[lk + 3][lr] = a4.w;
        Bs[lk + 0][lr] = b4.x; Bs[lk + 1][lr] = b4.y;
        Bs[lk + 2][lr] = b4.z; Bs[lk + 3][lr] = b4.w;
        __syncthreads();
#pragma unroll
        for (int k = 0; k < 8; k++) {
            float a[8], b[8];
#pragma unroll
            for (int i = 0; i < 8; i++) a[i] = As[k][ty * 8 + i];
#pragma unroll
            for (int j = 0; j < 8; j++) b[j] = Bs[k][tx * 8 + j];
#pragma unroll
            for (int i = 0; i < 8; i++)
#pragma unroll
                for (int j = 0; j < 8; j++) acc[i][j] += a[i] * b[j];
        }
        __syncthreads();
    }
#pragma unroll
    for (int i = 0; i < 8; i++) {
        float* cr = C + (size_t)(m0 + ty * 8 + i) * N + n0 + tx * 8;
#pragma unroll
        for (int j = 0; j < 8; j++) cr[j] = acc[i][j];
    }
}

// ---------------- per-head RMSNorm + RoPE + gain (q and k) ----------------
__global__ __launch_bounds__(128) void norm_rope_kernel(const float* __restrict__ gain) {
    int gw = (blockIdx.x * 128 + threadIdx.x) >> 5;
    int lane = threadIdx.x & 31;
    const int NQ = BB * TT * NH;
    const int NK = BB * TT * HKV;
    float* ptr;
    float g;
    int t;
    if (gw < NQ) {
        int h = gw % NH;
        int bt = gw / NH;
        t = bt % TT;
        ptr = g_q + ((size_t)bt * NH + h) * HD;
        g = gain[h];
    } else {
        int w2 = gw - NQ;
        if (w2 >= NK) return;
        int hk = w2 % HKV;
        int bt = w2 / HKV;
        t = bt % TT;
        ptr = g_k + ((size_t)bt * HKV + hk) * HD;
        g = 1.f;
    }
    float2 v = reinterpret_cast<const float2*>(ptr)[lane];
    float ss = v.x * v.x + v.y * v.y;
#pragma unroll
    for (int o = 16; o; o >>= 1) ss += __shfl_xor_sync(0xffffffffu, ss, o);
    float r = rsqrtf(ss * (1.f / 64.f) + 1.19209290e-07f);
    float n0 = v.x * r, n1 = v.y * r;
    float p0 = __shfl_xor_sync(0xffffffffu, n0, 8);
    float p1 = __shfl_xor_sync(0xffffffffu, n1, 8);
    float o0 = n0, o1 = n1;
    if (lane < 16) {
        int i0 = (2 * lane) & 15;           // freq index for first elem
        float inv0 = powf(10000.f, -(float)i0 * (1.f / 16.f));
        float inv1 = powf(10000.f, -(float)(i0 + 1) * (1.f / 16.f));
        float a0 = (float)t * inv0, a1 = (float)t * inv1;
        float c0 = cosf(a0), s0 = sinf(a0);
        float c1 = cosf(a1), s1 = sinf(a1);
        if (lane < 8) {                     // x1 half: x1*cos + x2*sin
            o0 = n0 * c0 + p0 * s0;
            o1 = n1 * c1 + p1 * s1;
        } else {                            // x2 half: -x1*sin + x2*cos
            o0 = -p0 * s0 + n0 * c0;
            o1 = -p1 * s1 + n1 * c1;
        }
    }
    reinterpret_cast<float2*>(ptr)[lane] = make_float2(o0 * g, o1 * g);
}

// ---------------- causal flash attention, fp32, 1 thread = 1 query row ----
__global__ __launch_bounds__(128) void attn_kernel() {
    __shared__ float Ks[64][64];
    __shared__ float Vs[64][64];
    int b = blockIdx.z, h = blockIdx.y, qt = blockIdx.x;
    int hk = h >> 2;
    int tid = threadIdx.x;
    int qi = qt * 128 + tid;

    float4 qv[16], acc[16];
    const float4* qp = reinterpret_cast<const float4*>(g_q + (((size_t)b * TT + qi) * NH + h) * HD);
#pragma unroll
    for (int i = 0; i < 16; i++) {
        qv[i] = qp[i];
        acc[i] = make_float4(0.f, 0.f, 0.f, 0.f);
    }
    float mx = -1e30f, l = 0.f;

    int ktmax = (qt * 128 + 127) >> 6;
    for (int kt = 0; kt <= ktmax; kt++) {
        // cooperative load of 64x64 K and V tiles
#pragma unroll
        for (int i = 0; i < 8; i++) {
            int f4 = tid + i * 128;            // 0..1023 float4 slots
            int rr = f4 >> 4;
            int dd = (f4 & 15) * 4;
            int kj = kt * 64 + rr;
            size_t base = (((size_t)b * TT + kj) * HKV + hk) * HD + dd;
            *reinterpret_cast<float4*>(&Ks[rr][dd]) = *reinterpret_cast<const float4*>(g_k + base);
            *reinterpret_cast<float4*>(&Vs[rr][dd]) = *reinterpret_cast<const float4*>(g_v + base);
        }
        __syncthreads();

        if (qi >= kt * 64) {
            int rel = qi - kt * 64;            // last valid j in this tile
#pragma unroll 1
            for (int jc = 0; jc < 64; jc += 8) {
                if (jc > rel) break;
                float s[8];
#pragma unroll
                for (int jj = 0; jj < 8; jj++) {
                    const float4* k4 = reinterpret_cast<const float4*>(&Ks[jc + jj][0]);
                    float s0 = 0.f, s1 = 0.f, s2 = 0.f, s3 = 0.f;
#pragma unroll
                    for (int i = 0; i < 16; i++) {
                        float4 kk = k4[i];
                        s0 += qv[i].x * kk.x;
                        s1 += qv[i].y * kk.y;
                        s2 += qv[i].z * kk.z;
                        s3 += qv[i].w * kk.w;
                    }
                    float sv = (s0 + s1) + (s2 + s3);
                    s[jj] = (jc + jj <= rel) ? sv * 0.125f : -1e30f;
                }
                float cm = s[0];
#pragma unroll
                for (int jj = 1; jj < 8; jj++) cm = fmaxf(cm, s[jj]);
                float m_new = fmaxf(mx, cm);
                float scale = __expf(mx - m_new);
                l *= scale;
#pragma unroll
                for (int i = 0; i < 16; i++) {
                    acc[i].x *= scale; acc[i].y *= scale;
                    acc[i].z *= scale; acc[i].w *= scale;
                }
#pragma unroll
                for (int jj = 0; jj < 8; jj++) {
                    float p = __expf(s[jj] - m_new);
                    l += p;
                    const float4* v4 = reinterpret_cast<const float4*>(&Vs[jc + jj][0]);
#pragma unroll
                    for (int i = 0; i < 16; i++) {
                        float4 vv = v4[i];
                        acc[i].x += p * vv.x; acc[i].y += p * vv.y;
                        acc[i].z += p * vv.z; acc[i].w += p * vv.w;
                    }
                }
                mx = m_new;
            }
        }
        __syncthreads();
    }
    float inv = 1.f / l;
    float4* yp = reinterpret_cast<float4*>(g_y + (((size_t)b * TT + qi) * NH + h) * HD);
#pragma unroll
    for (int i = 0; i < 16; i++)
        yp[i] = make_float4(acc[i].x * inv, acc[i].y * inv, acc[i].z * inv, acc[i].w * inv);
}

// ---------------- v-direction rejection: y - (y.vn) vn ----------------
__global__ __launch_bounds__(256) void vproj_kernel() {
    int gw = (blockIdx.x * 256 + threadIdx.x) >> 5;
    if (gw >= BB * TT * NH) return;
    int lane = threadIdx.x & 31;
    int h = gw % NH;
    int bt = gw / NH;
    int hk = h >> 2;
    float2 v = reinterpret_cast<const float2*>(g_v + ((size_t)bt * HKV + hk) * HD)[lane];
    float2 y = reinterpret_cast<const float2*>(g_y + ((size_t)bt * NH + h) * HD)[lane];
    float ns = v.x * v.x + v.y * v.y;
#pragma unroll
    for (int o = 16; o; o >>= 1) ns += __shfl_xor_sync(0xffffffffu, ns, o);
    float inv = 1.f / fmaxf(sqrtf(ns), 1e-12f);
    float vnx = v.x * inv, vny = v.y * inv;
    float dot = y.x * vnx + y.y * vny;
#pragma unroll
    for (int o = 16; o; o >>= 1) dot += __shfl_xor_sync(0xffffffffu, dot, o);
    float2 o2 = make_float2(y.x - dot * vnx, y.y - dot * vny);
    reinterpret_cast<float2*>(g_yo + ((size_t)bt * NH + h) * HD)[lane] = o2;
}

// ---------------- launch ----------------
extern "C" void kernel_launch(void* const* d_in, const int* in_sizes, int n_in,
                              void* d_out, int out_size) {
    const float* x      = (const float*)d_in[0];
    const float* w_q    = (const float*)d_in[1];
    const float* w_k    = (const float*)d_in[2];
    const float* w_v    = (const float*)d_in[3];
    const float* w_proj = (const float*)d_in[4];
    const float* q_gain = (const float*)d_in[5];

    float *wq, *wk, *wv, *wp, *q, *k, *v, *yo;
    cudaGetSymbolAddress((void**)&wq, g_wq);
    cudaGetSymbolAddress((void**)&wk, g_wk);
    cudaGetSymbolAddress((void**)&wv, g_wv);
    cudaGetSymbolAddress((void**)&wp, g_wp);
    cudaGetSymbolAddress((void**)&q, g_q);
    cudaGetSymbolAddress((void**)&k, g_k);
    cudaGetSymbolAddress((void**)&v, g_v);
    cudaGetSymbolAddress((void**)&yo, g_yo);

    const int M = BB * TT;          // 4096
    const int KVD = HKV * HD;       // 256

    // fake-quant weights: 6 bits -> half=32, 5 bits -> half=16
    quant_kernel<<<DIM, 256>>>(w_q, wq, DIM, 32.f);
    quant_kernel<<<KVD, 256>>>(w_k, wk, DIM, 32.f);
    quant_kernel<<<KVD, 256>>>(w_v, wv, DIM, 16.f);
    quant_kernel<<<DIM, 256>>>(w_proj, wp, DIM, 16.f);

    // QKV projections
    sgemm_nt<<<dim3(DIM / 128, M / 128), 256>>>(x, wq, q, M, DIM, DIM);
    sgemm_nt<<<dim3(KVD / 128, M / 128), 256>>>(x, wk, k, M, KVD, DIM);
    sgemm_nt<<<dim3(KVD / 128, M / 128), 256>>>(x, wv, v, M, KVD, DIM);

    // RMSNorm + RoPE + gain on q and k
    {
        int warps = BB * TT * (NH + HKV);   // 81920
        norm_rope_kernel<<<warps / 4, 128>>>(q_gain);
    }

    // causal attention
    attn_kernel<<<dim3(TT / 128, NH, BB), 128>>>();

    // v-direction rejection
    vproj_kernel<<<(BB * TT * NH) / 8, 256>>>();

    // output projection
    sgemm_nt<<<dim3(DIM / 128, M / 128), 256>>>(yo, wp, (float*)d_out, M, DIM, DIM);
}

// round 2
// speedup vs baseline: 1.5015x; 1.5015x over previous
#include <cuda_runtime.h>
#include <cuda_bf16.h>
#include <math.h>

#define BB 2
#define TT 2048
#define DIM 1024
#define NH 16
#define HKV 4
#define HD 64
#define GRP 4

// ---------------- scratch (device globals, no allocation) ----------------
__device__ float g_wq[DIM * DIM];
__device__ float g_wk[HKV * HD * DIM];
__device__ float g_wv[HKV * HD * DIM];
__device__ float g_wp[DIM * DIM];
__device__ float g_q[BB * TT * NH * HD];
__device__ float g_k[BB * TT * HKV * HD];
__device__ float g_v[BB * TT * HKV * HD];
__device__ float g_y[BB * TT * NH * HD];
__device__ float g_yo[BB * TT * DIM];

// ---------------- fake_quant: per-row max-abs quantize ----------------
__global__ __launch_bounds__(256) void quant_kernel(const float* __restrict__ W,
                                                    float* __restrict__ Wq,
                                                    int cols, float halfv) {
    __shared__ float red[256];
    int r = blockIdx.x;
    const float* row = W + (size_t)r * cols;
    float m = 0.f;
    for (int c = threadIdx.x; c < cols; c += 256) m = fmaxf(m, fabsf(row[c]));
    red[threadIdx.x] = m;
    __syncthreads();
    for (int s = 128; s > 0; s >>= 1) {
        if (threadIdx.x < s) red[threadIdx.x] = fmaxf(red[threadIdx.x], red[threadIdx.x + s]);
        __syncthreads();
    }
    float wmax = fmaxf(red[0], 1e-5f);
    float sc = halfv / wmax, isc = wmax / halfv;
    float* orow = Wq + (size_t)r * cols;
    for (int c = threadIdx.x; c < cols; c += 256) {
        float q = rintf(row[c] * sc);
        q = fminf(fmaxf(q, -halfv), halfv - 1.f);
        orow[c] = q * isc;
    }
}

// ---------------- tf32 tensor-core GEMM: C[M,N] = A[M,K] @ B[N,K]^T --------
// 128x128x32 tile, 256 threads (2x4 warps, 64x32 per warp), double-buffered.
#define PADK 36

__device__ __forceinline__ unsigned f2tf(float f) {
    unsigned u;
    asm("cvt.rna.tf32.f32 %0, %1;" : "=r"(u) : "f"(f));
    return u;
}

__global__ void __launch_bounds__(256) tf32_gemm_nt(const float* __restrict__ A,
                                                    const float* __restrict__ B,
                                                    float* __restrict__ C,
                                                    int M, int N, int K) {
    extern __shared__ float sm[];
    float* As = sm;                      // [2][128][PADK]
    float* Bs = sm + 2 * 128 * PADK;     // [2][128][PADK]

    const int tid = threadIdx.x;
    const int lane = tid & 31;
    const int wid = tid >> 5;
    const int wm = wid & 1;              // 0..1  (64 rows each)
    const int wn = wid >> 1;             // 0..3  (32 cols each)
    const int qr = lane >> 2;            // 0..7
    const int qc = lane & 3;             // 0..3
    const int m0 = blockIdx.y * 128, n0 = blockIdx.x * 128;
    const int lrow = tid >> 3;           // 0..31
    const int lk = (tid & 7) * 4;        // 0..28

    float acc[4][4][4] = {};
    float4 ra[4], rb[4];

    const int ntile = K / 32;

    // ---- load tile 0 into regs ----
#pragma unroll
    for (int p = 0; p < 4; p++) {
        ra[p] = *reinterpret_cast<const float4*>(A + (size_t)(m0 + lrow + p * 32) * K + lk);
        rb[p] = *reinterpret_cast<const float4*>(B + (size_t)(n0 + lrow + p * 32) * K + lk);
    }
    // ---- store tile 0 (tf32-converted) ----
#pragma unroll
    for (int p = 0; p < 4; p++) {
        float* as = As + (lrow + p * 32) * PADK + lk;
        float* bs = Bs + (lrow + p * 32) * PADK + lk;
        as[0] = __uint_as_float(f2tf(ra[p].x)); as[1] = __uint_as_float(f2tf(ra[p].y));
        as[2] = __uint_as_float(f2tf(ra[p].z)); as[3] = __uint_as_float(f2tf(ra[p].w));
        bs[0] = __uint_as_float(f2tf(rb[p].x)); bs[1] = __uint_as_float(f2tf(rb[p].y));
        bs[2] = __uint_as_float(f2tf(rb[p].z)); bs[3] = __uint_as_float(f2tf(rb[p].w));
    }
    __syncthreads();

    for (int t = 0; t < ntile; t++) {
        // prefetch next tile into registers
        if (t + 1 < ntile) {
            int koff = (t + 1) * 32 + lk;
#pragma unroll
            for (int p = 0; p < 4; p++) {
                ra[p] = *reinterpret_cast<const float4*>(A + (size_t)(m0 + lrow + p * 32) * K + koff);
                rb[p] = *reinterpret_cast<const float4*>(B + (size_t)(n0 + lrow + p * 32) * K + koff);
            }
        }
        // compute from buffer t&1
        const float* ab = As + (t & 1) * 128 * PADK;
        const float* bb = Bs + (t & 1) * 128 * PADK;
#pragma unroll
        for (int ks = 0; ks < 4; ks++) {
            int k0 = ks * 8;
            unsigned af[4][4], bf[4][2];
#pragma unroll
            for (int i = 0; i < 4; i++) {
                int mb = wm * 64 + i * 16;
                af[i][0] = __float_as_uint(ab[(mb + qr) * PADK + k0 + qc]);
                af[i][1] = __float_as_uint(ab[(mb + qr + 8) * PADK + k0 + qc]);
                af[i][2] = __float_as_uint(ab[(mb + qr) * PADK + k0 + qc + 4]);
                af[i][3] = __float_as_uint(ab[(mb + qr + 8) * PADK + k0 + qc + 4]);
            }
#pragma unroll
            for (int j = 0; j < 4; j++) {
                int nb = wn * 32 + j * 8;
                bf[j][0] = __float_as_uint(bb[(nb + qr) * PADK + k0 + qc]);
                bf[j][1] = __float_as_uint(bb[(nb + qr) * PADK + k0 + qc + 4]);
            }
#pragma unroll
            for (int i = 0; i < 4; i++)
#pragma unroll
                for (int j = 0; j < 4; j++) {
                    asm volatile(
                        "mma.sync.aligned.m16n8k8.row.col.f32.tf32.tf32.f32 "
                        "{%0,%1,%2,%3}, {%4,%5,%6,%7}, {%8,%9}, {%0,%1,%2,%3};\n"
                        : "+f"(acc[i][j][0]), "+f"(acc[i][j][1]),
                          "+f"(acc[i][j][2]), "+f"(acc[i][j][3])
                        : "r"(af[i][0]), "r"(af[i][1]), "r"(af[i][2]), "r"(af[i][3]),
                          "r"(bf[j][0]), "r"(bf[j][1]));
                }
        }
        // store prefetched tile into the other buffer
        if (t + 1 < ntile) {
            float* as = As + ((t + 1) & 1) * 128 * PADK;
            float* bs = Bs + ((t + 1) & 1) * 128 * PADK;
#pragma unroll
            for (int p = 0; p < 4; p++) {
                float* ar = as + (lrow + p * 32) * PADK + lk;
                float* br = bs + (lrow + p * 32) * PADK + lk;
                ar[0] = __uint_as_float(f2tf(ra[p].x)); ar[1] = __uint_as_float(f2tf(ra[p].y));
                ar[2] = __uint_as_float(f2tf(ra[p].z)); ar[3] = __uint_as_float(f2tf(ra[p].w));
                br[0] = __uint_as_float(f2tf(rb[p].x)); br[1] = __uint_as_float(f2tf(rb[p].y));
                br[2] = __uint_as_float(f2tf(rb[p].z)); br[3] = __uint_as_float(f2tf(rb[p].w));
            }
        }
        __syncthreads();
    }

    // ---- epilogue ----
#pragma unroll
    for (int i = 0; i < 4; i++) {
        int row = m0 + wm * 64 + i * 16 + qr;
#pragma unroll
        for (int j = 0; j < 4; j++) {
            int col = n0 + wn * 32 + j * 8 + 2 * qc;
            *reinterpret_cast<float2*>(C + (size_t)row * N + col) =
                make_float2(acc[i][j][0], acc[i][j][1]);
            *reinterpret_cast<float2*>(C + (size_t)(row + 8) * N + col) =
                make_float2(acc[i][j][2], acc[i][j][3]);
        }
    }
}

// ---------------- per-head RMSNorm + RoPE + gain (q and k) ----------------
__global__ __launch_bounds__(128) void norm_rope_kernel(const float* __restrict__ gain) {
    int gw = (blockIdx.x * 128 + threadIdx.x) >> 5;
    int lane = threadIdx.x & 31;
    const int NQ = BB * TT * NH;
    const int NK = BB * TT * HKV;
    float* ptr;
    float g;
    int t;
    if (gw < NQ) {
        int h = gw % NH;
        int bt = gw / NH;
        t = bt % TT;
        ptr = g_q + ((size_t)bt * NH + h) * HD;
        g = gain[h];
    } else {
        int w2 = gw - NQ;
        if (w2 >= NK) return;
        int hk = w2 % HKV;
        int bt = w2 / HKV;
        t = bt % TT;
        ptr = g_k + ((size_t)bt * HKV + hk) * HD;
        g = 1.f;
    }
    float2 v = reinterpret_cast<const float2*>(ptr)[lane];
    float ss = v.x * v.x + v.y * v.y;
#pragma unroll
    for (int o = 16; o; o >>= 1) ss += __shfl_xor_sync(0xffffffffu, ss, o);
    float r = rsqrtf(ss * (1.f / 64.f) + 1.19209290e-07f);
    float n0 = v.x * r, n1 = v.y * r;
    float p0 = __shfl_xor_sync(0xffffffffu, n0, 8);
    float p1 = __shfl_xor_sync(0xffffffffu, n1, 8);
    float o0 = n0, o1 = n1;
    if (lane < 16) {
        int i0 = (2 * lane) & 15;
        float inv0 = powf(10000.f, -(float)i0 * (1.f / 16.f));
        float inv1 = powf(10000.f, -(float)(i0 + 1) * (1.f / 16.f));
        float a0 = (float)t * inv0, a1 = (float)t * inv1;
        float c0 = cosf(a0), s0 = sinf(a0);
        float c1 = cosf(a1), s1 = sinf(a1);
        if (lane < 8) {
            o0 = n0 * c0 + p0 * s0;
            o1 = n1 * c1 + p1 * s1;
        } else {
            o0 = -p0 * s0 + n0 * c0;
            o1 = -p1 * s1 + n1 * c1;
        }
    }
    reinterpret_cast<float2*>(ptr)[lane] = make_float2(o0 * g, o1 * g);
}

// ---------------- causal flash attention, fp32, 1 thread = 1 query row ----
__global__ __launch_bounds__(128) void attn_kernel() {
    __shared__ float Ks[64][64];
    __shared__ float Vs[64][64];
    int b = blockIdx.z, h = blockIdx.y, qt = blockIdx.x;
    int hk = h >> 2;
    int tid = threadIdx.x;
    int qi = qt * 128 + tid;

    float4 qv[16], acc[16];
    const float4* qp = reinterpret_cast<const float4*>(g_q + (((size_t)b * TT + qi) * NH + h) * HD);
#pragma unroll
    for (int i = 0; i < 16; i++) {
        qv[i] = qp[i];
        acc[i] = make_float4(0.f, 0.f, 0.f, 0.f);
    }
    float mx = -1e30f, l = 0.f;

    int ktmax = (qt * 128 + 127) >> 6;
    for (int kt = 0; kt <= ktmax; kt++) {
#pragma unroll
        for (int i = 0; i < 8; i++) {
            int f4 = tid + i * 128;
            int rr = f4 >> 4;
            int dd = (f4 & 15) * 4;
            int kj = kt * 64 + rr;
            size_t base = (((size_t)b * TT + kj) * HKV + hk) * HD + dd;
            *reinterpret_cast<float4*>(&Ks[rr][dd]) = *reinterpret_cast<const float4*>(g_k + base);
            *reinterpret_cast<float4*>(&Vs[rr][dd]) = *reinterpret_cast<const float4*>(g_v + base);
        }
        __syncthreads();

        if (qi >= kt * 64) {
            int rel = qi - kt * 64;
#pragma unroll 1
            for (int jc = 0; jc < 64; jc += 8) {
                if (jc > rel) break;
                float s[8];
#pragma unroll
                for (int jj = 0; jj < 8; jj++) {
                    const float4* k4 = reinterpret_cast<const float4*>(&Ks[jc + jj][0]);
                    float s0 = 0.f, s1 = 0.f, s2 = 0.f, s3 = 0.f;
#pragma unroll
                    for (int i = 0; i < 16; i++) {
                        float4 kk = k4[i];
                        s0 += qv[i].x * kk.x;
                        s1 += qv[i].y * kk.y;
                        s2 += qv[i].z * kk.z;
                        s3 += qv[i].w * kk.w;
                    }
                    float sv = (s0 + s1) + (s2 + s3);
                    s[jj] = (jc + jj <= rel) ? sv * 0.125f : -1e30f;
                }
                float cm = s[0];
#pragma unroll
                for (int jj = 1; jj < 8; jj++) cm = fmaxf(cm, s[jj]);
                float m_new = fmaxf(mx, cm);
                float scale = __expf(mx - m_new);
                l *= scale;
#pragma unroll
                for (int i = 0; i < 16; i++) {
                    acc[i].x *= scale; acc[i].y *= scale;
                    acc[i].z *= scale; acc[i].w *= scale;
                }
#pragma unroll
                for (int jj = 0; jj < 8; jj++) {
                    float p = __expf(s[jj] - m_new);
                    l += p;
                    const float4* v4 = reinterpret_cast<const float4*>(&Vs[jc + jj][0]);
#pragma unroll
                    for (int i = 0; i < 16; i++) {
                        float4 vv = v4[i];
                        acc[i].x += p * vv.x; acc[i].y += p * vv.y;
                        acc[i].z += p * vv.z; acc[i].w += p * vv.w;
                    }
                }
                mx = m_new;
            }
        }
        __syncthreads();
    }
    float inv = 1.f / l;
    float4* yp = reinterpret_cast<float4*>(g_y + (((size_t)b * TT + qi) * NH + h) * HD);
#pragma unroll
    for (int i = 0; i < 16; i++)
        yp[i] = make_float4(acc[i].x * inv, acc[i].y * inv, acc[i].z * inv, acc[i].w * inv);
}

// ---------------- v-direction rejection: y - (y.vn) vn ----------------
__global__ __launch_bounds__(256) void vproj_kernel() {
    int gw = (blockIdx.x * 256 + threadIdx.x) >> 5;
    if (gw >= BB * TT * NH) return;
    int lane = threadIdx.x & 31;
    int h = gw % NH;
    int bt = gw / NH;
    int hk = h >> 2;
    float2 v = reinterpret_cast<const float2*>(g_v + ((size_t)bt * HKV + hk) * HD)[lane];
    float2 y = reinterpret_cast<const float2*>(g_y + ((size_t)bt * NH + h) * HD)[lane];
    float ns = v.x * v.x + v.y * v.y;
#pragma unroll
    for (int o = 16; o; o >>= 1) ns += __shfl_xor_sync(0xffffffffu, ns, o);
    float inv = 1.f / fmaxf(sqrtf(ns), 1e-12f);
    float vnx = v.x * inv, vny = v.y * inv;
    float dot = y.x * vnx + y.y * vny;
#pragma unroll
    for (int o = 16; o; o >>= 1) dot += __shfl_xor_sync(0xffffffffu, dot, o);
    float2 o2 = make_float2(y.x - dot * vnx, y.y - dot * vny);
    reinterpret_cast<float2*>(g_yo + ((size_t)bt * NH + h) * HD)[lane] = o2;
}

// ---------------- launch ----------------
extern "C" void kernel_launch(void* const* d_in, const int* in_sizes, int n_in,
                              void* d_out, int out_size) {
    const float* x      = (const float*)d_in[0];
    const float* w_q    = (const float*)d_in[1];
    const float* w_k    = (const float*)d_in[2];
    const float* w_v    = (const float*)d_in[3];
    const float* w_proj = (const float*)d_in[4];
    const float* q_gain = (const float*)d_in[5];

    float *wq, *wk, *wv, *wp, *q, *k, *v, *yo;
    cudaGetSymbolAddress((void**)&wq, g_wq);
    cudaGetSymbolAddress((void**)&wk, g_wk);
    cudaGetSymbolAddress((void**)&wv, g_wv);
    cudaGetSymbolAddress((void**)&wp, g_wp);
    cudaGetSymbolAddress((void**)&q, g_q);
    cudaGetSymbolAddress((void**)&k, g_k);
    cudaGetSymbolAddress((void**)&v, g_v);
    cudaGetSymbolAddress((void**)&yo, g_yo);

    const int M = BB * TT;          // 4096
    const int KVD = HKV * HD;       // 256
    const int SMEM = 4 * 128 * PADK * sizeof(float);   // 73728 bytes

    static bool attr_set = false;
    if (!attr_set) {
        cudaFuncSetAttribute(tf32_gemm_nt, cudaFuncAttributeMaxDynamicSharedMemorySize, SMEM);
        attr_set = true;
    }

    // fake-quant weights: 6 bits -> half=32, 5 bits -> half=16
    quant_kernel<<<DIM, 256>>>(w_q, wq, DIM, 32.f);
    quant_kernel<<<KVD, 256>>>(w_k, wk, DIM, 32.f);
    quant_kernel<<<KVD, 256>>>(w_v, wv, DIM, 16.f);
    quant_kernel<<<DIM, 256>>>(w_proj, wp, DIM, 16.f);

    // QKV projections (tf32 tensor cores)
    tf32_gemm_nt<<<dim3(DIM / 128, M / 128), 256, SMEM>>>(x, wq, q, M, DIM, DIM);
    tf32_gemm_nt<<<dim3(KVD / 128, M / 128), 256, SMEM>>>(x, wk, k, M, KVD, DIM);
    tf32_gemm_nt<<<dim3(KVD / 128, M / 128), 256, SMEM>>>(x, wv, v, M, KVD, DIM);

    // RMSNorm + RoPE + gain on q and k
    {
        int warps = BB * TT * (NH + HKV);
        norm_rope_kernel<<<warps / 4, 128>>>(q_gain);
    }

    // causal attention
    attn_kernel<<<dim3(TT / 128, NH, BB), 128>>>();

    // v-direction rejection
    vproj_kernel<<<(BB * TT * NH) / 8, 256>>>();

    // output projection (tf32 tensor cores)
    tf32_gemm_nt<<<dim3(DIM / 128, M / 128), 256, SMEM>>>(yo, wp, (float*)d_out, M, DIM, DIM);
}

// round 3
// speedup vs baseline: 1.7723x; 1.1803x over previous
#include <cuda_runtime.h>
#include <cuda_bf16.h>
#include <math.h>

#define BB 2
#define TT 2048
#define DIM 1024
#define NH 16
#define HKV 4
#define HD 64
#define GRP 4

// ---------------- scratch (device globals, no allocation) ----------------
__device__ float g_wq[DIM * DIM];
__device__ float g_wk[HKV * HD * DIM];
__device__ float g_wv[HKV * HD * DIM];
__device__ float g_wp[DIM * DIM];
__device__ float g_q[BB * TT * NH * HD];
__device__ float g_k[BB * TT * HKV * HD];
__device__ float g_v[BB * TT * HKV * HD];
__device__ float g_y[BB * TT * NH * HD];
__device__ float g_yo[BB * TT * DIM];

// ---------------- tf32 helpers ----------------
__device__ __forceinline__ unsigned f2tf(float f) {
    unsigned u;
    asm("cvt.rna.tf32.f32 %0, %1;" : "=r"(u) : "f"(f));
    return u;
}
__device__ __forceinline__ void split2(float f, unsigned& hi, unsigned& lo) {
    unsigned h = f2tf(f);
    hi = h;
    lo = f2tf(f - __uint_as_float(h));
}

#define MMA_TF32(C, A0, A1, A2, A3, B0, B1)                                   \
    asm volatile(                                                             \
        "mma.sync.aligned.m16n8k8.row.col.f32.tf32.tf32.f32 "                 \
        "{%0,%1,%2,%3}, {%4,%5,%6,%7}, {%8,%9}, {%0,%1,%2,%3};\n"             \
        : "+f"(C[0]), "+f"(C[1]), "+f"(C[2]), "+f"(C[3])                      \
        : "r"(A0), "r"(A1), "r"(A2), "r"(A3), "r"(B0), "r"(B1))

// ---------------- fake_quant: per-row max-abs quantize ----------------
__global__ __launch_bounds__(256) void quant_kernel(const float* __restrict__ W,
                                                    float* __restrict__ Wq,
                                                    int cols, float halfv) {
    __shared__ float red[256];
    int r = blockIdx.x;
    const float* row = W + (size_t)r * cols;
    float m = 0.f;
    for (int c = threadIdx.x; c < cols; c += 256) m = fmaxf(m, fabsf(row[c]));
    red[threadIdx.x] = m;
    __syncthreads();
    for (int s = 128; s > 0; s >>= 1) {
        if (threadIdx.x < s) red[threadIdx.x] = fmaxf(red[threadIdx.x], red[threadIdx.x + s]);
        __syncthreads();
    }
    float wmax = fmaxf(red[0], 1e-5f);
    float sc = halfv / wmax, isc = wmax / halfv;
    float* orow = Wq + (size_t)r * cols;
    for (int c = threadIdx.x; c < cols; c += 256) {
        float q = rintf(row[c] * sc);
        q = fminf(fmaxf(q, -halfv), halfv - 1.f);
        orow[c] = q * isc;
    }
}

// ---------------- 3xTF32 tensor-core GEMM: C[M,N] = A[M,K] @ B[N,K]^T ------
#define PADK 36

__global__ void __launch_bounds__(256) tf32_gemm_nt(const float* __restrict__ A,
                                                    const float* __restrict__ B,
                                                    float* __restrict__ C,
                                                    int M, int N, int K) {
    extern __shared__ float sm[];
    float* As = sm;                      // [2][128][PADK]
    float* Bs = sm + 2 * 128 * PADK;     // [2][128][PADK]

    const int tid = threadIdx.x;
    const int lane = tid & 31;
    const int wid = tid >> 5;
    const int wm = wid & 1;
    const int wn = wid >> 1;
    const int qr = lane >> 2;
    const int qc = lane & 3;
    const int m0 = blockIdx.y * 128, n0 = blockIdx.x * 128;
    const int lrow = tid >> 3;
    const int lk = (tid & 7) * 4;

    float acc[4][4][4] = {};
    float4 ra[4], rb[4];

    const int ntile = K / 32;

#pragma unroll
    for (int p = 0; p < 4; p++) {
        ra[p] = *reinterpret_cast<const float4*>(A + (size_t)(m0 + lrow + p * 32) * K + lk);
        rb[p] = *reinterpret_cast<const float4*>(B + (size_t)(n0 + lrow + p * 32) * K + lk);
    }
#pragma unroll
    for (int p = 0; p < 4; p++) {
        *reinterpret_cast<float4*>(As + (lrow + p * 32) * PADK + lk) = ra[p];
        *reinterpret_cast<float4*>(Bs + (lrow + p * 32) * PADK + lk) = rb[p];
    }
    __syncthreads();

    for (int t = 0; t < ntile; t++) {
        if (t + 1 < ntile) {
            int koff = (t + 1) * 32 + lk;
#pragma unroll
            for (int p = 0; p < 4; p++) {
                ra[p] = *reinterpret_cast<const float4*>(A + (size_t)(m0 + lrow + p * 32) * K + koff);
                rb[p] = *reinterpret_cast<const float4*>(B + (size_t)(n0 + lrow + p * 32) * K + koff);
            }
        }
        const float* ab = As + (t & 1) * 128 * PADK;
        const float* bb = Bs + (t & 1) * 128 * PADK;
#pragma unroll
        for (int ks = 0; ks < 4; ks++) {
            int k0 = ks * 8;
            unsigned ah[4][4], al[4][4], bh[4][2], bl[4][2];
#pragma unroll
            for (int i = 0; i < 4; i++) {
                int mb = wm * 64 + i * 16;
                split2(ab[(mb + qr) * PADK + k0 + qc],     ah[i][0], al[i][0]);
                split2(ab[(mb + qr + 8) * PADK + k0 + qc], ah[i][1], al[i][1]);
                split2(ab[(mb + qr) * PADK + k0 + qc + 4],     ah[i][2], al[i][2]);
                split2(ab[(mb + qr + 8) * PADK + k0 + qc + 4], ah[i][3], al[i][3]);
            }
#pragma unroll
            for (int j = 0; j < 4; j++) {
                int nb = wn * 32 + j * 8;
                split2(bb[(nb + qr) * PADK + k0 + qc],     bh[j][0], bl[j][0]);
                split2(bb[(nb + qr) * PADK + k0 + qc + 4], bh[j][1], bl[j][1]);
            }
#pragma unroll
            for (int i = 0; i < 4; i++)
#pragma unroll
                for (int j = 0; j < 4; j++) {
                    MMA_TF32(acc[i][j], ah[i][0], ah[i][1], ah[i][2], ah[i][3], bh[j][0], bh[j][1]);
                    MMA_TF32(acc[i][j], al[i][0], al[i][1], al[i][2], al[i][3], bh[j][0], bh[j][1]);
                    MMA_TF32(acc[i][j], ah[i][0], ah[i][1], ah[i][2], ah[i][3], bl[j][0], bl[j][1]);
                }
        }
        if (t + 1 < ntile) {
            float* as = As + ((t + 1) & 1) * 128 * PADK;
            float* bs = Bs + ((t + 1) & 1) * 128 * PADK;
#pragma unroll
            for (int p = 0; p < 4; p++) {
                *reinterpret_cast<float4*>(as + (lrow + p * 32) * PADK + lk) = ra[p];
                *reinterpret_cast<float4*>(bs + (lrow + p * 32) * PADK + lk) = rb[p];
            }
        }
        __syncthreads();
    }

#pragma unroll
    for (int i = 0; i < 4; i++) {
        int row = m0 + wm * 64 + i * 16 + qr;
#pragma unroll
        for (int j = 0; j < 4; j++) {
            int col = n0 + wn * 32 + j * 8 + 2 * qc;
            *reinterpret_cast<float2*>(C + (size_t)row * N + col) =
                make_float2(acc[i][j][0], acc[i][j][1]);
            *reinterpret_cast<float2*>(C + (size_t)(row + 8) * N + col) =
                make_float2(acc[i][j][2], acc[i][j][3]);
        }
    }
}

// ---------------- per-head RMSNorm + RoPE + gain (q and k) ----------------
__global__ __launch_bounds__(128) void norm_rope_kernel(const float* __restrict__ gain) {
    int gw = (blockIdx.x * 128 + threadIdx.x) >> 5;
    int lane = threadIdx.x & 31;
    const int NQ = BB * TT * NH;
    const int NK = BB * TT * HKV;
    float* ptr;
    float g;
    int t;
    if (gw < NQ) {
        int h = gw % NH;
        int bt = gw / NH;
        t = bt % TT;
        ptr = g_q + ((size_t)bt * NH + h) * HD;
        g = gain[h];
    } else {
        int w2 = gw - NQ;
        if (w2 >= NK) return;
        int hk = w2 % HKV;
        int bt = w2 / HKV;
        t = bt % TT;
        ptr = g_k + ((size_t)bt * HKV + hk) * HD;
        g = 1.f;
    }
    float2 v = reinterpret_cast<const float2*>(ptr)[lane];
    float ss = v.x * v.x + v.y * v.y;
#pragma unroll
    for (int o = 16; o; o >>= 1) ss += __shfl_xor_sync(0xffffffffu, ss, o);
    float r = rsqrtf(ss * (1.f / 64.f) + 1.19209290e-07f);
    float n0 = v.x * r, n1 = v.y * r;
    float p0 = __shfl_xor_sync(0xffffffffu, n0, 8);
    float p1 = __shfl_xor_sync(0xffffffffu, n1, 8);
    float o0 = n0, o1 = n1;
    if (lane < 16) {
        int i0 = (2 * lane) & 15;
        float inv0 = powf(10000.f, -(float)i0 * (1.f / 16.f));
        float inv1 = powf(10000.f, -(float)(i0 + 1) * (1.f / 16.f));
        float a0 = (float)t * inv0, a1 = (float)t * inv1;
        float c0 = cosf(a0), s0 = sinf(a0);
        float c1 = cosf(a1), s1 = sinf(a1);
        if (lane < 8) {
            o0 = n0 * c0 + p0 * s0;
            o1 = n1 * c1 + p1 * s1;
        } else {
            o0 = -p0 * s0 + n0 * c0;
            o1 = -p1 * s1 + n1 * c1;
        }
    }
    reinterpret_cast<float2*>(ptr)[lane] = make_float2(o0 * g, o1 * g);
}

// ---------------- tensor-core causal flash attention (3xTF32) -------------
// BM=128 (8 warps x m16), BN=64, D=64
#define ATP 72

__global__ void __launch_bounds__(256) attn_tc_kernel() {
    extern __shared__ float sm[];
    float* Ks = sm;                     // [64][ATP]
    float* Vs = sm + 64 * ATP;          // [64][ATP]
    float* Ps = sm + 2 * 64 * ATP;      // [128][ATP]

    const int b = blockIdx.z, h = blockIdx.y, qt = blockIdx.x;
    const int hk = h >> 2;
    const int tid = threadIdx.x;
    const int lane = tid & 31;
    const int w = tid >> 5;
    const int qr = lane >> 2;
    const int qc = lane & 3;
    const int qbase = qt * 128 + w * 16;
    const int qi0 = qbase + qr, qi1 = qbase + qr + 8;

    // Q fragments (hi/lo), reused across all K tiles
    unsigned qh[8][4], ql[8][4];
    {
        const float* Qp = g_q + (((size_t)b * TT + qbase) * NH + h) * HD;
#pragma unroll
        for (int ks = 0; ks < 8; ks++) {
            int c0 = ks * 8 + qc;
            split2(Qp[qr * (NH * HD) + c0],           qh[ks][0], ql[ks][0]);
            split2(Qp[(qr + 8) * (NH * HD) + c0],     qh[ks][1], ql[ks][1]);
            split2(Qp[qr * (NH * HD) + c0 + 4],       qh[ks][2], ql[ks][2]);
            split2(Qp[(qr + 8) * (NH * HD) + c0 + 4], qh[ks][3], ql[ks][3]);
        }
    }

    float yac[8][4] = {};
    float m0 = -1e30f, m1 = -1e30f, l0 = 0.f, l1 = 0.f;

    const int ktmax = 2 * qt + 1;
    for (int kt = 0; kt <= ktmax; kt++) {
        // cooperative load of K,V 64x64 tiles
#pragma unroll
        for (int i = 0; i < 4; i++) {
            int f4 = tid + i * 256;
            int rr = f4 >> 4;
            int dd = (f4 & 15) * 4;
            size_t base = (((size_t)b * TT + kt * 64 + rr) * HKV + hk) * HD + dd;
            *reinterpret_cast<float4*>(Ks + rr * ATP + dd) =
                *reinterpret_cast<const float4*>(g_k + base);
            *reinterpret_cast<float4*>(Vs + rr * ATP + dd) =
                *reinterpret_cast<const float4*>(g_v + base);
        }
        __syncthreads();

        if (kt * 64 <= qbase + 15) {
            // ---- S = Q K^T (3xTF32) ----
            float sf[8][4] = {};
#pragma unroll
            for (int ks = 0; ks < 8; ks++) {
                int k0 = ks * 8;
#pragma unroll
                for (int j = 0; j < 8; j++) {
                    unsigned bh0, bl0, bh1, bl1;
                    split2(Ks[(j * 8 + qr) * ATP + k0 + qc],     bh0, bl0);
                    split2(Ks[(j * 8 + qr) * ATP + k0 + qc + 4], bh1, bl1);
                    MMA_TF32(sf[j], qh[ks][0], qh[ks][1], qh[ks][2], qh[ks][3], bh0, bh1);
                    MMA_TF32(sf[j], ql[ks][0], ql[ks][1], ql[ks][2], ql[ks][3], bh0, bh1);
                    MMA_TF32(sf[j], qh[ks][0], qh[ks][1], qh[ks][2], qh[ks][3], bl0, bl1);
                }
            }
            // ---- scale + causal mask ----
#pragma unroll
            for (int j = 0; j < 8; j++) {
                int kj = kt * 64 + j * 8 + 2 * qc;
                sf[j][0] = (kj     <= qi0) ? sf[j][0] * 0.125f : -1e30f;
                sf[j][1] = (kj + 1 <= qi0) ? sf[j][1] * 0.125f : -1e30f;
                sf[j][2] = (kj     <= qi1) ? sf[j][2] * 0.125f : -1e30f;
                sf[j][3] = (kj + 1 <= qi1) ? sf[j][3] * 0.125f : -1e30f;
            }
            // ---- online softmax ----
            float cm0 = -1e30f, cm1 = -1e30f;
#pragma unroll
            for (int j = 0; j < 8; j++) {
                cm0 = fmaxf(cm0, fmaxf(sf[j][0], sf[j][1]));
                cm1 = fmaxf(cm1, fmaxf(sf[j][2], sf[j][3]));
            }
            cm0 = fmaxf(cm0, __shfl_xor_sync(0xffffffffu, cm0, 1));
            cm0 = fmaxf(cm0, __shfl_xor_sync(0xffffffffu, cm0, 2));
            cm1 = fmaxf(cm1, __shfl_xor_sync(0xffffffffu, cm1, 1));
            cm1 = fmaxf(cm1, __shfl_xor_sync(0xffffffffu, cm1, 2));
            float mn0 = fmaxf(m0, cm0), mn1 = fmaxf(m1, cm1);
            float a0 = __expf(m0 - mn0), a1 = __expf(m1 - mn1);
#pragma unroll
            for (int jd = 0; jd < 8; jd++) {
                yac[jd][0] *= a0; yac[jd][1] *= a0;
                yac[jd][2] *= a1; yac[jd][3] *= a1;
            }
            float rs0 = 0.f, rs1 = 0.f;
#pragma unroll
            for (int j = 0; j < 8; j++) {
                float p0 = __expf(sf[j][0] - mn0);
                float p1 = __expf(sf[j][1] - mn0);
                float p2 = __expf(sf[j][2] - mn1);
                float p3 = __expf(sf[j][3] - mn1);
                rs0 += p0 + p1; rs1 += p2 + p3;
                int col = j * 8 + 2 * qc;
                *reinterpret_cast<float2*>(Ps + (w * 16 + qr) * ATP + col) = make_float2(p0, p1);
                *reinterpret_cast<float2*>(Ps + (w * 16 + qr + 8) * ATP + col) = make_float2(p2, p3);
            }
            rs0 += __shfl_xor_sync(0xffffffffu, rs0, 1);
            rs0 += __shfl_xor_sync(0xffffffffu, rs0, 2);
            rs1 += __shfl_xor_sync(0xffffffffu, rs1, 1);
            rs1 += __shfl_xor_sync(0xffffffffu, rs1, 2);
            l0 = l0 * a0 + rs0;
            l1 = l1 * a1 + rs1;
            m0 = mn0; m1 = mn1;
            __syncwarp();
            // ---- Y += P V (3xTF32) ----
#pragma unroll
            for (int ks = 0; ks < 8; ks++) {
                int k0 = ks * 8;
                unsigned ph[4], pl[4];
                split2(Ps[(w * 16 + qr) * ATP + k0 + qc],         ph[0], pl[0]);
                split2(Ps[(w * 16 + qr + 8) * ATP + k0 + qc],     ph[1], pl[1]);
                split2(Ps[(w * 16 + qr) * ATP + k0 + qc + 4],     ph[2], pl[2]);
                split2(Ps[(w * 16 + qr + 8) * ATP + k0 + qc + 4], ph[3], pl[3]);
#pragma unroll
                for (int jd = 0; jd < 8; jd++) {
                    unsigned vh0, vl0, vh1, vl1;
                    split2(Vs[(k0 + qc) * ATP + jd * 8 + qr],     vh0, vl0);
                    split2(Vs[(k0 + qc + 4) * ATP + jd * 8 + qr], vh1, vl1);
                    MMA_TF32(yac[jd], ph[0], ph[1], ph[2], ph[3], vh0, vh1);
                    MMA_TF32(yac[jd], pl[0], pl[1], pl[2], pl[3], vh0, vh1);
                    MMA_TF32(yac[jd], ph[0], ph[1], ph[2], ph[3], vl0, vl1);
                }
            }
            __syncwarp();
        }
        __syncthreads();
    }

    float inv0 = 1.f / l0, inv1 = 1.f / l1;
    float* Yp = g_y + (((size_t)b * TT + qbase) * NH + h) * HD;
#pragma unroll
    for (int jd = 0; jd < 8; jd++) {
        int col = jd * 8 + 2 * qc;
        *reinterpret_cast<float2*>(Yp + qr * (NH * HD) + col) =
            make_float2(yac[jd][0] * inv0, yac[jd][1] * inv0);
        *reinterpret_cast<float2*>(Yp + (qr + 8) * (NH * HD) + col) =
            make_float2(yac[jd][2] * inv1, yac[jd][3] * inv1);
    }
}

// ---------------- v-direction rejection: y - (y.vn) vn ----------------
__global__ __launch_bounds__(256) void vproj_kernel() {
    int gw = (blockIdx.x * 256 + threadIdx.x) >> 5;
    if (gw >= BB * TT * NH) return;
    int lane = threadIdx.x & 31;
    int h = gw % NH;
    int bt = gw / NH;
    int hk = h >> 2;
    float2 v = reinterpret_cast<const float2*>(g_v + ((size_t)bt * HKV + hk) * HD)[lane];
    float2 y = reinterpret_cast<const float2*>(g_y + ((size_t)bt * NH + h) * HD)[lane];
    float ns = v.x * v.x + v.y * v.y;
#pragma unroll
    for (int o = 16; o; o >>= 1) ns += __shfl_xor_sync(0xffffffffu, ns, o);
    float inv = 1.f / fmaxf(sqrtf(ns), 1e-12f);
    float vnx = v.x * inv, vny = v.y * inv;
    float dot = y.x * vnx + y.y * vny;
#pragma unroll
    for (int o = 16; o; o >>= 1) dot += __shfl_xor_sync(0xffffffffu, dot, o);
    float2 o2 = make_float2(y.x - dot * vnx, y.y - dot * vny);
    reinterpret_cast<float2*>(g_yo + ((size_t)bt * NH + h) * HD)[lane] = o2;
}

// ---------------- launch ----------------
extern "C" void kernel_launch(void* const* d_in, const int* in_sizes, int n_in,
                              void* d_out, int out_size) {
    const float* x      = (const float*)d_in[0];
    const float* w_q    = (const float*)d_in[1];
    const float* w_k    = (const float*)d_in[2];
    const float* w_v    = (const float*)d_in[3];
    const float* w_proj = (const float*)d_in[4];
    const float* q_gain = (const float*)d_in[5];

    float *wq, *wk, *wv, *wp, *q, *k, *v, *yo;
    cudaGetSymbolAddress((void**)&wq, g_wq);
    cudaGetSymbolAddress((void**)&wk, g_wk);
    cudaGetSymbolAddress((void**)&wv, g_wv);
    cudaGetSymbolAddress((void**)&wp, g_wp);
    cudaGetSymbolAddress((void**)&q, g_q);
    cudaGetSymbolAddress((void**)&k, g_k);
    cudaGetSymbolAddress((void**)&v, g_v);
    cudaGetSymbolAddress((void**)&yo, g_yo);

    const int M = BB * TT;          // 4096
    const int KVD = HKV * HD;       // 256
    const int SMEM = 4 * 128 * PADK * sizeof(float);       // 73728
    const int ASMEM = (2 * 64 * ATP + 128 * ATP) * sizeof(float);  // 73728

    static bool attr_set = false;
    if (!attr_set) {
        cudaFuncSetAttribute(tf32_gemm_nt, cudaFuncAttributeMaxDynamicSharedMemorySize, SMEM);
        cudaFuncSetAttribute(attn_tc_kernel, cudaFuncAttributeMaxDynamicSharedMemorySize, ASMEM);
        attr_set = true;
    }

    quant_kernel<<<DIM, 256>>>(w_q, wq, DIM, 32.f);
    quant_kernel<<<KVD, 256>>>(w_k, wk, DIM, 32.f);
    quant_kernel<<<KVD, 256>>>(w_v, wv, DIM, 16.f);
    quant_kernel<<<DIM, 256>>>(w_proj, wp, DIM, 16.f);

    tf32_gemm_nt<<<dim3(DIM / 128, M / 128), 256, SMEM>>>(x, wq, q, M, DIM, DIM);
    tf32_gemm_nt<<<dim3(KVD / 128, M / 128), 256, SMEM>>>(x, wk, k, M, KVD, DIM);
    tf32_gemm_nt<<<dim3(KVD / 128, M / 128), 256, SMEM>>>(x, wv, v, M, KVD, DIM);

    {
        int warps = BB * TT * (NH + HKV);
        norm_rope_kernel<<<warps / 4, 128>>>(q_gain);
    }

    attn_tc_kernel<<<dim3(TT / 128, NH, BB), 256, ASMEM>>>();

    vproj_kernel<<<(BB * TT * NH) / 8, 256>>>();

    tf32_gemm_nt<<<dim3(DIM / 128, M / 128), 256, SMEM>>>(yo, wp, (float*)d_out, M, DIM, DIM);
}

// round 6
// speedup vs baseline: 3.4324x; 1.9368x over previous
#include <cuda_runtime.h>
#include <cuda_bf16.h>
#include <math.h>

#define BB 2
#define TT 2048
#define DIM 1024
#define NH 16
#define HKV 4
#define HD 64
#define GRP 4

// ---------------- scratch (device globals, no allocation) ----------------
__device__ float g_wq[DIM * DIM];
__device__ float g_wk[HKV * HD * DIM];
__device__ float g_wv[HKV * HD * DIM];
__device__ float g_wp[DIM * DIM];
__device__ float g_q[BB * TT * NH * HD];
__device__ float g_k[BB * TT * HKV * HD];
__device__ float g_v[BB * TT * HKV * HD];
__device__ float g_y[BB * TT * NH * HD];
__device__ float g_yo[BB * TT * DIM];

// ---------------- bf16 split helpers ----------------
// pack (x,y) as bf16x2 hi, and the residual as bf16x2 lo (k-adjacent pair)
__device__ __forceinline__ void splitbf(float x, float y, unsigned& hi, unsigned& lo) {
    __nv_bfloat162 h = __floats2bfloat162_rn(x, y);
    float hx = __low2float(h), hy = __high2float(h);
    __nv_bfloat162 l = __floats2bfloat162_rn(x - hx, y - hy);
    hi = *reinterpret_cast<unsigned*>(&h);
    lo = *reinterpret_cast<unsigned*>(&l);
}

#define MMA_BF16(C, A0, A1, A2, A3, B0, B1)                                   \
    asm volatile(                                                             \
        "mma.sync.aligned.m16n8k16.row.col.f32.bf16.bf16.f32 "                \
        "{%0,%1,%2,%3}, {%4,%5,%6,%7}, {%8,%9}, {%0,%1,%2,%3};\n"             \
        : "+f"(C[0]), "+f"(C[1]), "+f"(C[2]), "+f"(C[3])                      \
        : "r"(A0), "r"(A1), "r"(A2), "r"(A3), "r"(B0), "r"(B1))

// ---------------- fake_quant: per-row max-abs quantize ----------------
__global__ __launch_bounds__(256) void quant_kernel(const float* __restrict__ W,
                                                    float* __restrict__ Wq,
                                                    int cols, float halfv) {
    __shared__ float red[256];
    int r = blockIdx.x;
    const float* row = W + (size_t)r * cols;
    float m = 0.f;
    for (int c = threadIdx.x; c < cols; c += 256) m = fmaxf(m, fabsf(row[c]));
    red[threadIdx.x] = m;
    __syncthreads();
    for (int s = 128; s > 0; s >>= 1) {
        if (threadIdx.x < s) red[threadIdx.x] = fmaxf(red[threadIdx.x], red[threadIdx.x + s]);
        __syncthreads();
    }
    float wmax = fmaxf(red[0], 1e-5f);
    float sc = halfv / wmax, isc = wmax / halfv;
    float* orow = Wq + (size_t)r * cols;
    for (int c = threadIdx.x; c < cols; c += 256) {
        float q = rintf(row[c] * sc);
        q = fminf(fmaxf(q, -halfv), halfv - 1.f);
        orow[c] = q * isc;
    }
}

// ---------------- 3x-bf16 tensor-core GEMM: C[M,N] = A[M,K] @ B[N,K]^T -----
// 128x128x32 tile, 256 threads (2x4 warps, 64x32 per warp), double-buffered.
// Smem holds pre-split bf16 hi/lo packed as k-adjacent pairs (uint32).
#define KP 20   // uint32 row stride: 16 kpairs + 4 pad (conflict-free fragment LDS)

__global__ void __launch_bounds__(256) bf16_gemm_nt(const float* __restrict__ A,
                                                    const float* __restrict__ B,
                                                    float* __restrict__ C,
                                                    int M, int N, int K) {
    extern __shared__ unsigned smu[];
    unsigned* Ah = smu;                   // [2][128][KP]
    unsigned* Al = smu + 2 * 128 * KP;
    unsigned* Bh = smu + 4 * 128 * KP;
    unsigned* Bl = smu + 6 * 128 * KP;

    const int tid = threadIdx.x;
    const int lane = tid & 31;
    const int wid = tid >> 5;
    const int wm = wid & 1;
    const int wn = wid >> 1;
    const int qr = lane >> 2;
    const int qc = lane & 3;
    const int m0 = blockIdx.y * 128, n0 = blockIdx.x * 128;
    const int lrow = tid >> 3;
    const int lkf = (tid & 7) * 4;
    const int kp0 = (tid & 7) * 2;

    float acc[4][4][4] = {};
    float4 ra[4], rb[4];
    const int ntile = K / 32;

#pragma unroll
    for (int p = 0; p < 4; p++) {
        ra[p] = *reinterpret_cast<const float4*>(A + (size_t)(m0 + lrow + p * 32) * K + lkf);
        rb[p] = *reinterpret_cast<const float4*>(B + (size_t)(n0 + lrow + p * 32) * K + lkf);
    }
    // stage tile 0
#pragma unroll
    for (int p = 0; p < 4; p++) {
        int row = lrow + p * 32;
        unsigned h0, l0, h1, l1;
        splitbf(ra[p].x, ra[p].y, h0, l0);
        splitbf(ra[p].z, ra[p].w, h1, l1);
        Ah[row * KP + kp0] = h0; Ah[row * KP + kp0 + 1] = h1;
        Al[row * KP + kp0] = l0; Al[row * KP + kp0 + 1] = l1;
        splitbf(rb[p].x, rb[p].y, h0, l0);
        splitbf(rb[p].z, rb[p].w, h1, l1);
        Bh[row * KP + kp0] = h0; Bh[row * KP + kp0 + 1] = h1;
        Bl[row * KP + kp0] = l0; Bl[row * KP + kp0 + 1] = l1;
    }
    __syncthreads();

    for (int t = 0; t < ntile; t++) {
        if (t + 1 < ntile) {
            int koff = (t + 1) * 32 + lkf;
#pragma unroll
            for (int p = 0; p < 4; p++) {
                ra[p] = *reinterpret_cast<const float4*>(A + (size_t)(m0 + lrow + p * 32) * K + koff);
                rb[p] = *reinterpret_cast<const float4*>(B + (size_t)(n0 + lrow + p * 32) * K + koff);
            }
        }
        const unsigned* ah_b = Ah + (t & 1) * 128 * KP;
        const unsigned* al_b = Al + (t & 1) * 128 * KP;
        const unsigned* bh_b = Bh + (t & 1) * 128 * KP;
        const unsigned* bl_b = Bl + (t & 1) * 128 * KP;
#pragma unroll
        for (int ks = 0; ks < 2; ks++) {
            int kb = ks * 8 + qc;
            unsigned afh[4][4], afl[4][4], bfh[4][2], bfl[4][2];
#pragma unroll
            for (int i = 0; i < 4; i++) {
                int r0 = (wm * 64 + i * 16 + qr) * KP;
                int r8 = r0 + 8 * KP;
                afh[i][0] = ah_b[r0 + kb];     afh[i][1] = ah_b[r8 + kb];
                afh[i][2] = ah_b[r0 + kb + 4]; afh[i][3] = ah_b[r8 + kb + 4];
                afl[i][0] = al_b[r0 + kb];     afl[i][1] = al_b[r8 + kb];
                afl[i][2] = al_b[r0 + kb + 4]; afl[i][3] = al_b[r8 + kb + 4];
            }
#pragma unroll
            for (int j = 0; j < 4; j++) {
                int r0 = (wn * 32 + j * 8 + qr) * KP;
                bfh[j][0] = bh_b[r0 + kb]; bfh[j][1] = bh_b[r0 + kb + 4];
                bfl[j][0] = bl_b[r0 + kb]; bfl[j][1] = bl_b[r0 + kb + 4];
            }
#pragma unroll
            for (int i = 0; i < 4; i++)
#pragma unroll
                for (int j = 0; j < 4; j++) {
                    MMA_BF16(acc[i][j], afh[i][0], afh[i][1], afh[i][2], afh[i][3], bfh[j][0], bfh[j][1]);
                    MMA_BF16(acc[i][j], afl[i][0], afl[i][1], afl[i][2], afl[i][3], bfh[j][0], bfh[j][1]);
                    MMA_BF16(acc[i][j], afh[i][0], afh[i][1], afh[i][2], afh[i][3], bfl[j][0], bfl[j][1]);
                }
        }
        if (t + 1 < ntile) {
            unsigned* ah_n = Ah + ((t + 1) & 1) * 128 * KP;
            unsigned* al_n = Al + ((t + 1) & 1) * 128 * KP;
            unsigned* bh_n = Bh + ((t + 1) & 1) * 128 * KP;
            unsigned* bl_n = Bl + ((t + 1) & 1) * 128 * KP;
#pragma unroll
            for (int p = 0; p < 4; p++) {
                int row = lrow + p * 32;
                unsigned h0, l0, h1, l1;
                splitbf(ra[p].x, ra[p].y, h0, l0);
                splitbf(ra[p].z, ra[p].w, h1, l1);
                ah_n[row * KP + kp0] = h0; ah_n[row * KP + kp0 + 1] = h1;
                al_n[row * KP + kp0] = l0; al_n[row * KP + kp0 + 1] = l1;
                splitbf(rb[p].x, rb[p].y, h0, l0);
                splitbf(rb[p].z, rb[p].w, h1, l1);
                bh_n[row * KP + kp0] = h0; bh_n[row * KP + kp0 + 1] = h1;
                bl_n[row * KP + kp0] = l0; bl_n[row * KP + kp0 + 1] = l1;
            }
        }
        __syncthreads();
    }

#pragma unroll
    for (int i = 0; i < 4; i++) {
        int row = m0 + wm * 64 + i * 16 + qr;
#pragma unroll
        for (int j = 0; j < 4; j++) {
            int col = n0 + wn * 32 + j * 8 + 2 * qc;
            *reinterpret_cast<float2*>(C + (size_t)row * N + col) =
                make_float2(acc[i][j][0], acc[i][j][1]);
            *reinterpret_cast<float2*>(C + (size_t)(row + 8) * N + col) =
                make_float2(acc[i][j][2], acc[i][j][3]);
        }
    }
}

// ---------------- per-head RMSNorm + RoPE + gain (q and k) ----------------
__global__ __launch_bounds__(128) void norm_rope_kernel(const float* __restrict__ gain) {
    int gw = (blockIdx.x * 128 + threadIdx.x) >> 5;
    int lane = threadIdx.x & 31;
    const int NQ = BB * TT * NH;
    const int NK = BB * TT * HKV;
    float* ptr;
    float g;
    int t;
    if (gw < NQ) {
        int h = gw % NH;
        int bt = gw / NH;
        t = bt % TT;
        ptr = g_q + ((size_t)bt * NH + h) * HD;
        g = gain[h];
    } else {
        int w2 = gw - NQ;
        if (w2 >= NK) return;
        int hk = w2 % HKV;
        int bt = w2 / HKV;
        t = bt % TT;
        ptr = g_k + ((size_t)bt * HKV + hk) * HD;
        g = 1.f;
    }
    float2 v = reinterpret_cast<const float2*>(ptr)[lane];
    float ss = v.x * v.x + v.y * v.y;
#pragma unroll
    for (int o = 16; o; o >>= 1) ss += __shfl_xor_sync(0xffffffffu, ss, o);
    float r = rsqrtf(ss * (1.f / 64.f) + 1.19209290e-07f);
    float n0 = v.x * r, n1 = v.y * r;
    float p0 = __shfl_xor_sync(0xffffffffu, n0, 8);
    float p1 = __shfl_xor_sync(0xffffffffu, n1, 8);
    float o0 = n0, o1 = n1;
    if (lane < 16) {
        int i0 = (2 * lane) & 15;
        float inv0 = powf(10000.f, -(float)i0 * (1.f / 16.f));
        float inv1 = powf(10000.f, -(float)(i0 + 1) * (1.f / 16.f));
        float a0 = (float)t * inv0, a1 = (float)t * inv1;
        float c0 = cosf(a0), s0 = sinf(a0);
        float c1 = cosf(a1), s1 = sinf(a1);
        if (lane < 8) {
            o0 = n0 * c0 + p0 * s0;
            o1 = n1 * c1 + p1 * s1;
        } else {
            o0 = -p0 * s0 + n0 * c0;
            o1 = -p1 * s1 + n1 * c1;
        }
    }
    reinterpret_cast<float2*>(ptr)[lane] = make_float2(o0 * g, o1 * g);
}

// ---------------- tensor-core causal flash attention (3x-bf16) -------------
// BM=128 (8 warps x m16), BN=64, D=64. Register-resident P.
// Smem: K hi/lo packed along d (stride 36), V hi/lo packed along key-pairs,
// transposed (stride 72). All conflict-free for the fragment access patterns.
#define KSTR 36
#define VSTR 72

__global__ void __launch_bounds__(256) attn_tc_kernel() {
    extern __shared__ unsigned smu[];
    unsigned* Khi = smu;                  // [64][KSTR]
    unsigned* Klo = smu + 64 * KSTR;
    unsigned* Vph = smu + 2 * 64 * KSTR;  // [32][VSTR]
    unsigned* Vpl = smu + 2 * 64 * KSTR + 32 * VSTR;

    const int b = blockIdx.z, h = blockIdx.y, qt = blockIdx.x;
    const int hk = h >> 2;
    const int tid = threadIdx.x;
    const int lane = tid & 31;
    const int w = tid >> 5;
    const int qr = lane >> 2;
    const int qc = lane & 3;
    const int qbase = qt * 128 + w * 16;
    const int qi0 = qbase + qr, qi1 = qbase + qr + 8;

    // Q fragments (bf16 hi/lo packed pairs), reused across all K tiles
    unsigned qh[4][4], ql[4][4];
    {
        const float* Qp = g_q + (((size_t)b * TT + qbase) * NH + h) * HD;
#pragma unroll
        for (int ks = 0; ks < 4; ks++) {
            int c0 = ks * 16 + 2 * qc;
            float2 x0 = *reinterpret_cast<const float2*>(Qp + qr * (NH * HD) + c0);
            float2 x1 = *reinterpret_cast<const float2*>(Qp + (qr + 8) * (NH * HD) + c0);
            float2 x2 = *reinterpret_cast<const float2*>(Qp + qr * (NH * HD) + c0 + 8);
            float2 x3 = *reinterpret_cast<const float2*>(Qp + (qr + 8) * (NH * HD) + c0 + 8);
            splitbf(x0.x, x0.y, qh[ks][0], ql[ks][0]);
            splitbf(x1.x, x1.y, qh[ks][1], ql[ks][1]);
            splitbf(x2.x, x2.y, qh[ks][2], ql[ks][2]);
            splitbf(x3.x, x3.y, qh[ks][3], ql[ks][3]);
        }
    }

    float yac[8][4] = {};
    float m0 = -1e30f, m1 = -1e30f, l0 = 0.f, l1 = 0.f;

    const int ktmax = 2 * qt + 1;
    for (int kt = 0; kt <= ktmax; kt++) {
        // ---- stage K tile: split + pack along d ----
#pragma unroll
        for (int i = 0; i < 4; i++) {
            int it = tid + i * 256;               // 0..1023
            int rr = it >> 4;
            int ddf = (it & 15) * 4;
            size_t base = (((size_t)b * TT + kt * 64 + rr) * HKV + hk) * HD + ddf;
            float4 kv = *reinterpret_cast<const float4*>(g_k + base);
            unsigned h0, l0r, h1, l1r;
            splitbf(kv.x, kv.y, h0, l0r);
            splitbf(kv.z, kv.w, h1, l1r);
            int o = rr * KSTR + ddf / 2;
            Khi[o] = h0; Khi[o + 1] = h1;
            Klo[o] = l0r; Klo[o + 1] = l1r;
        }
        // ---- stage V tile: split + pack along key pairs, transposed ----
#pragma unroll
        for (int i = 0; i < 2; i++) {
            int it = tid + i * 256;               // 0..511
            int r2 = it >> 4;                     // key pair 0..31
            int ddf = (it & 15) * 4;
            size_t base = (((size_t)b * TT + kt * 64 + 2 * r2) * HKV + hk) * HD + ddf;
            float4 v0 = *reinterpret_cast<const float4*>(g_v + base);
            float4 v1 = *reinterpret_cast<const float4*>(g_v + base + HKV * HD);
            int o = r2 * VSTR + ddf;
            unsigned hh, ll;
            splitbf(v0.x, v1.x, hh, ll); Vph[o] = hh;     Vpl[o] = ll;
            splitbf(v0.y, v1.y, hh, ll); Vph[o + 1] = hh; Vpl[o + 1] = ll;
            splitbf(v0.z, v1.z, hh, ll); Vph[o + 2] = hh; Vpl[o + 2] = ll;
            splitbf(v0.w, v1.w, hh, ll); Vph[o + 3] = hh; Vpl[o + 3] = ll;
        }
        __syncthreads();

        if (kt * 64 <= qbase + 15) {
            // ---- S = Q K^T (3x bf16) ----
            float sf[8][4] = {};
#pragma unroll
            for (int ks = 0; ks < 4; ks++) {
#pragma unroll
                for (int j = 0; j < 8; j++) {
                    int kb = (j * 8 + qr) * KSTR + ks * 8 + qc;
                    unsigned kh0 = Khi[kb], kh1 = Khi[kb + 4];
                    unsigned kl0 = Klo[kb], kl1 = Klo[kb + 4];
                    MMA_BF16(sf[j], qh[ks][0], qh[ks][1], qh[ks][2], qh[ks][3], kh0, kh1);
                    MMA_BF16(sf[j], ql[ks][0], ql[ks][1], ql[ks][2], ql[ks][3], kh0, kh1);
                    MMA_BF16(sf[j], qh[ks][0], qh[ks][1], qh[ks][2], qh[ks][3], kl0, kl1);
                }
            }
            // ---- scale + causal mask ----
#pragma unroll
            for (int j = 0; j < 8; j++) {
                int kj = kt * 64 + j * 8 + 2 * qc;
                sf[j][0] = (kj     <= qi0) ? sf[j][0] * 0.125f : -1e30f;
                sf[j][1] = (kj + 1 <= qi0) ? sf[j][1] * 0.125f : -1e30f;
                sf[j][2] = (kj     <= qi1) ? sf[j][2] * 0.125f : -1e30f;
                sf[j][3] = (kj + 1 <= qi1) ? sf[j][3] * 0.125f : -1e30f;
            }
            // ---- online softmax ----
            float cm0 = -1e30f, cm1 = -1e30f;
#pragma unroll
            for (int j = 0; j < 8; j++) {
                cm0 = fmaxf(cm0, fmaxf(sf[j][0], sf[j][1]));
                cm1 = fmaxf(cm1, fmaxf(sf[j][2], sf[j][3]));
            }
            cm0 = fmaxf(cm0, __shfl_xor_sync(0xffffffffu, cm0, 1));
            cm0 = fmaxf(cm0, __shfl_xor_sync(0xffffffffu, cm0, 2));
            cm1 = fmaxf(cm1, __shfl_xor_sync(0xffffffffu, cm1, 1));
            cm1 = fmaxf(cm1, __shfl_xor_sync(0xffffffffu, cm1, 2));
            float mn0 = fmaxf(m0, cm0), mn1 = fmaxf(m1, cm1);
            float a0 = __expf(m0 - mn0), a1 = __expf(m1 - mn1);
#pragma unroll
            for (int jd = 0; jd < 8; jd++) {
                yac[jd][0] *= a0; yac[jd][1] *= a0;
                yac[jd][2] *= a1; yac[jd][3] *= a1;
            }
            // ---- P = exp(S - m), register-resident bf16 hi/lo frags ----
            unsigned ph0[8], ph1[8], pl0[8], pl1[8];
            float rs0 = 0.f, rs1 = 0.f;
#pragma unroll
            for (int j = 0; j < 8; j++) {
                float p0 = __expf(sf[j][0] - mn0);
                float p1 = __expf(sf[j][1] - mn0);
                float p2 = __expf(sf[j][2] - mn1);
                float p3 = __expf(sf[j][3] - mn1);
                rs0 += p0 + p1; rs1 += p2 + p3;
                splitbf(p0, p1, ph0[j], pl0[j]);
                splitbf(p2, p3, ph1[j], pl1[j]);
            }
            rs0 += __shfl_xor_sync(0xffffffffu, rs0, 1);
            rs0 += __shfl_xor_sync(0xffffffffu, rs0, 2);
            rs1 += __shfl_xor_sync(0xffffffffu, rs1, 1);
            rs1 += __shfl_xor_sync(0xffffffffu, rs1, 2);
            l0 = l0 * a0 + rs0;
            l1 = l1 * a1 + rs1;
            m0 = mn0; m1 = mn1;
            // ---- Y += P V (3x bf16), P from registers ----
#pragma unroll
            for (int ks = 0; ks < 4; ks++) {
                unsigned a0h = ph0[2 * ks], a1h = ph1[2 * ks];
                unsigned a2h = ph0[2 * ks + 1], a3h = ph1[2 * ks + 1];
                unsigned a0l = pl0[2 * ks], a1l = pl1[2 * ks];
                unsigned a2l = pl0[2 * ks + 1], a3l = pl1[2 * ks + 1];
#pragma unroll
                for (int jd = 0; jd < 8; jd++) {
                    int vb = (ks * 8 + qc) * VSTR + jd * 8 + qr;
                    unsigned vh0 = Vph[vb], vh1 = Vph[vb + 4 * VSTR];
                    unsigned vl0 = Vpl[vb], vl1 = Vpl[vb + 4 * VSTR];
                    MMA_BF16(yac[jd], a0h, a1h, a2h, a3h, vh0, vh1);
                    MMA_BF16(yac[jd], a0l, a1l, a2l, a3l, vh0, vh1);
                    MMA_BF16(yac[jd], a0h, a1h, a2h, a3h, vl0, vl1);
                }
            }
        }
        __syncthreads();
    }

    float inv0 = 1.f / l0, inv1 = 1.f / l1;
    float* Yp = g_y + (((size_t)b * TT + qbase) * NH + h) * HD;
#pragma unroll
    for (int jd = 0; jd < 8; jd++) {
        int col = jd * 8 + 2 * qc;
        *reinterpret_cast<float2*>(Yp + qr * (NH * HD) + col) =
            make_float2(yac[jd][0] * inv0, yac[jd][1] * inv0);
        *reinterpret_cast<float2*>(Yp + (qr + 8) * (NH * HD) + col) =
            make_float2(yac[jd][2] * inv1, yac[jd][3] * inv1);
    }
}

// ---------------- v-direction rejection: y - (y.vn) vn ----------------
__global__ __launch_bounds__(256) void vproj_kernel() {
    int gw = (blockIdx.x * 256 + threadIdx.x) >> 5;
    if (gw >= BB * TT * NH) return;
    int lane = threadIdx.x & 31;
    int h = gw % NH;
    int bt = gw / NH;
    int hk = h >> 2;
    float2 v = reinterpret_cast<const float2*>(g_v + ((size_t)bt * HKV + hk) * HD)[lane];
    float2 y = reinterpret_cast<const float2*>(g_y + ((size_t)bt * NH + h) * HD)[lane];
    float ns = v.x * v.x + v.y * v.y;
#pragma unroll
    for (int o = 16; o; o >>= 1) ns += __shfl_xor_sync(0xffffffffu, ns, o);
    float inv = 1.f / fmaxf(sqrtf(ns), 1e-12f);
    float vnx = v.x * inv, vny = v.y * inv;
    float dot = y.x * vnx + y.y * vny;
#pragma unroll
    for (int o = 16; o; o >>= 1) dot += __shfl_xor_sync(0xffffffffu, dot, o);
    float2 o2 = make_float2(y.x - dot * vnx, y.y - dot * vny);
    reinterpret_cast<float2*>(g_yo + ((size_t)bt * NH + h) * HD)[lane] = o2;
}

// ---------------- launch ----------------
extern "C" void kernel_launch(void* const* d_in, const int* in_sizes, int n_in,
                              void* d_out, int out_size) {
    const float* x      = (const float*)d_in[0];
    const float* w_q    = (const float*)d_in[1];
    const float* w_k    = (const float*)d_in[2];
    const float* w_v    = (const float*)d_in[3];
    const float* w_proj = (const float*)d_in[4];
    const float* q_gain = (const float*)d_in[5];

    float *wq, *wk, *wv, *wp, *q, *k, *v, *yo;
    cudaGetSymbolAddress((void**)&wq, g_wq);
    cudaGetSymbolAddress((void**)&wk, g_wk);
    cudaGetSymbolAddress((void**)&wv, g_wv);
    cudaGetSymbolAddress((void**)&wp, g_wp);
    cudaGetSymbolAddress((void**)&q, g_q);
    cudaGetSymbolAddress((void**)&k, g_k);
    cudaGetSymbolAddress((void**)&v, g_v);
    cudaGetSymbolAddress((void**)&yo, g_yo);

    const int M = BB * TT;          // 4096
    const int KVD = HKV * HD;       // 256
    const int SMEM = 8 * 128 * KP * sizeof(unsigned);                     // 81920
    const int ASMEM = (2 * 64 * KSTR + 2 * 32 * VSTR) * sizeof(unsigned); // 36864

    static bool attr_set = false;
    if (!attr_set) {
        cudaFuncSetAttribute(bf16_gemm_nt, cudaFuncAttributeMaxDynamicSharedMemorySize, SMEM);
        cudaFuncSetAttribute(attn_tc_kernel, cudaFuncAttributeMaxDynamicSharedMemorySize, ASMEM);
        attr_set = true;
    }

    quant_kernel<<<DIM, 256>>>(w_q, wq, DIM, 32.f);
    quant_kernel<<<KVD, 256>>>(w_k, wk, DIM, 32.f);
    quant_kernel<<<KVD, 256>>>(w_v, wv, DIM, 16.f);
    quant_kernel<<<DIM, 256>>>(w_proj, wp, DIM, 16.f);

    bf16_gemm_nt<<<dim3(DIM / 128, M / 128), 256, SMEM>>>(x, wq, q, M, DIM, DIM);
    bf16_gemm_nt<<<dim3(KVD / 128, M / 128), 256, SMEM>>>(x, wk, k, M, KVD, DIM);
    bf16_gemm_nt<<<dim3(KVD / 128, M / 128), 256, SMEM>>>(x, wv, v, M, KVD, DIM);

    {
        int warps = BB * TT * (NH + HKV);
        norm_rope_kernel<<<warps / 4, 128>>>(q_gain);
    }

    attn_tc_kernel<<<dim3(TT / 128, NH, BB), 256, ASMEM>>>();

    vproj_kernel<<<(BB * TT * NH) / 8, 256>>>();

    bf16_gemm_nt<<<dim3(DIM / 128, M / 128), 256, SMEM>>>(yo, wp, (float*)d_out, M, DIM, DIM);
}

// round 7
// speedup vs baseline: 3.9466x; 1.1498x over previous
#include <cuda_runtime.h>
#include <cuda_bf16.h>
#include <math.h>

#define BB 2
#define TT 2048
#define DIM 1024
#define NH 16
#define HKV 4
#define HD 64
#define NQKV 1536   // 1024 q + 256 k + 256 v

// ---------------- scratch (device globals, no allocation) ----------------
__device__ float g_w[NQKV * DIM];        // fused quantized wq|wk|wv (row-major, [1536][1024])
__device__ float g_wp[DIM * DIM];
__device__ float g_qkv[BB * TT * NQKV];  // fused q|k|v activations per token
__device__ float g_yo[BB * TT * DIM];

// ---------------- bf16 split helpers ----------------
__device__ __forceinline__ void splitbf(float x, float y, unsigned& hi, unsigned& lo) {
    __nv_bfloat162 h = __floats2bfloat162_rn(x, y);
    float hx = __low2float(h), hy = __high2float(h);
    __nv_bfloat162 l = __floats2bfloat162_rn(x - hx, y - hy);
    hi = *reinterpret_cast<unsigned*>(&h);
    lo = *reinterpret_cast<unsigned*>(&l);
}

#define MMA_BF16(C, A0, A1, A2, A3, B0, B1)                                   \
    asm volatile(                                                             \
        "mma.sync.aligned.m16n8k16.row.col.f32.bf16.bf16.f32 "                \
        "{%0,%1,%2,%3}, {%4,%5,%6,%7}, {%8,%9}, {%0,%1,%2,%3};\n"             \
        : "+f"(C[0]), "+f"(C[1]), "+f"(C[2]), "+f"(C[3])                      \
        : "r"(A0), "r"(A1), "r"(A2), "r"(A3), "r"(B0), "r"(B1))

__device__ __forceinline__ void ldsm4(unsigned& r0, unsigned& r1, unsigned& r2, unsigned& r3,
                                      const unsigned* p) {
    unsigned addr = (unsigned)__cvta_generic_to_shared(p);
    asm volatile("ldmatrix.sync.aligned.m8n8.x4.shared.b16 {%0,%1,%2,%3}, [%4];"
                 : "=r"(r0), "=r"(r1), "=r"(r2), "=r"(r3) : "r"(addr));
}

// ---------------- fake_quant kernels ----------------
__device__ __forceinline__ void quant_row(const float* __restrict__ row,
                                          float* __restrict__ orow, float halfv) {
    __shared__ float red[256];
    float m = 0.f;
    for (int c = threadIdx.x; c < DIM; c += 256) m = fmaxf(m, fabsf(row[c]));
    red[threadIdx.x] = m;
    __syncthreads();
    for (int s = 128; s > 0; s >>= 1) {
        if (threadIdx.x < s) red[threadIdx.x] = fmaxf(red[threadIdx.x], red[threadIdx.x + s]);
        __syncthreads();
    }
    float wmax = fmaxf(red[0], 1e-5f);
    float sc = halfv / wmax, isc = wmax / halfv;
    for (int c = threadIdx.x; c < DIM; c += 256) {
        float q = rintf(row[c] * sc);
        q = fminf(fmaxf(q, -halfv), halfv - 1.f);
        orow[c] = q * isc;
    }
}

__global__ __launch_bounds__(256) void quant_fused_kernel(const float* __restrict__ wq,
                                                          const float* __restrict__ wk,
                                                          const float* __restrict__ wv,
                                                          float* __restrict__ out) {
    int r = blockIdx.x;
    const float* src;
    float halfv;
    if (r < 1024) { src = wq + (size_t)r * DIM; halfv = 32.f; }
    else if (r < 1280) { src = wk + (size_t)(r - 1024) * DIM; halfv = 32.f; }
    else { src = wv + (size_t)(r - 1280) * DIM; halfv = 16.f; }
    quant_row(src, out + (size_t)r * DIM, halfv);
}

__global__ __launch_bounds__(256) void quant_kernel(const float* __restrict__ W,
                                                    float* __restrict__ Wq, float halfv) {
    int r = blockIdx.x;
    quant_row(W + (size_t)r * DIM, Wq + (size_t)r * DIM, halfv);
}

// ---------------- 3x-bf16 tensor-core GEMM: C[M,N] = A[M,K] @ B[N,K]^T -----
// 128x128x32 tile, 256 threads (2x4 warps, 64x32/warp), double-buffered smem
// with pre-split bf16 hi/lo k-pairs; fragments loaded via ldmatrix.x4.
#define KP 20

__global__ void __launch_bounds__(256) bf16_gemm_nt(const float* __restrict__ A,
                                                    const float* __restrict__ B,
                                                    float* __restrict__ C,
                                                    int M, int N, int K) {
    extern __shared__ unsigned smu[];
    unsigned* Ah = smu;                   // [2][128][KP]
    unsigned* Al = smu + 2 * 128 * KP;
    unsigned* Bh = smu + 4 * 128 * KP;
    unsigned* Bl = smu + 6 * 128 * KP;

    const int tid = threadIdx.x;
    const int lane = tid & 31;
    const int wid = tid >> 5;
    const int wm = wid & 1;
    const int wn = wid >> 1;
    const int qr = lane >> 2;
    const int qc = lane & 3;
    const int m0 = blockIdx.y * 128, n0 = blockIdx.x * 128;
    const int lrow = tid >> 3;
    const int lkf = (tid & 7) * 4;
    const int kp0 = (tid & 7) * 2;

    // ldmatrix lane addressing
    const int lt = lane >> 3, lr = lane & 7;
    const int baseA = (wm * 64 + lr + (lt & 1) * 8) * KP + (lt >> 1) * 4;
    const int baseB = (wn * 32 + lr) * KP + (lt & 1) * 4;
    const int jrowB = (lt >> 1) * 8 * KP;

    float acc[4][4][4] = {};
    float4 ra[4], rb[4];
    const int ntile = K / 32;

#pragma unroll
    for (int p = 0; p < 4; p++) {
        ra[p] = *reinterpret_cast<const float4*>(A + (size_t)(m0 + lrow + p * 32) * K + lkf);
        rb[p] = *reinterpret_cast<const float4*>(B + (size_t)(n0 + lrow + p * 32) * K + lkf);
    }
#pragma unroll
    for (int p = 0; p < 4; p++) {
        int row = lrow + p * 32;
        unsigned h0, l0, h1, l1;
        splitbf(ra[p].x, ra[p].y, h0, l0);
        splitbf(ra[p].z, ra[p].w, h1, l1);
        Ah[row * KP + kp0] = h0; Ah[row * KP + kp0 + 1] = h1;
        Al[row * KP + kp0] = l0; Al[row * KP + kp0 + 1] = l1;
        splitbf(rb[p].x, rb[p].y, h0, l0);
        splitbf(rb[p].z, rb[p].w, h1, l1);
        Bh[row * KP + kp0] = h0; Bh[row * KP + kp0 + 1] = h1;
        Bl[row * KP + kp0] = l0; Bl[row * KP + kp0 + 1] = l1;
    }
    __syncthreads();

    for (int t = 0; t < ntile; t++) {
        if (t + 1 < ntile) {
            int koff = (t + 1) * 32 + lkf;
#pragma unroll
            for (int p = 0; p < 4; p++) {
                ra[p] = *reinterpret_cast<const float4*>(A + (size_t)(m0 + lrow + p * 32) * K + koff);
                rb[p] = *reinterpret_cast<const float4*>(B + (size_t)(n0 + lrow + p * 32) * K + koff);
            }
        }
        const unsigned* ah_b = Ah + (t & 1) * 128 * KP;
        const unsigned* al_b = Al + (t & 1) * 128 * KP;
        const unsigned* bh_b = Bh + (t & 1) * 128 * KP;
        const unsigned* bl_b = Bl + (t & 1) * 128 * KP;
#pragma unroll
        for (int ks = 0; ks < 2; ks++) {
            unsigned afh[4][4], afl[4][4], bfh[4][2], bfl[4][2];
#pragma unroll
            for (int i = 0; i < 4; i++) {
                int o = baseA + i * 16 * KP + ks * 8;
                ldsm4(afh[i][0], afh[i][1], afh[i][2], afh[i][3], ah_b + o);
                ldsm4(afl[i][0], afl[i][1], afl[i][2], afl[i][3], al_b + o);
            }
#pragma unroll
            for (int jp = 0; jp < 2; jp++) {
                int o = baseB + (jp * 2) * 8 * KP + jrowB + ks * 8;
                ldsm4(bfh[2 * jp][0], bfh[2 * jp][1], bfh[2 * jp + 1][0], bfh[2 * jp + 1][1], bh_b + o);
                ldsm4(bfl[2 * jp][0], bfl[2 * jp][1], bfl[2 * jp + 1][0], bfl[2 * jp + 1][1], bl_b + o);
            }
#pragma unroll
            for (int i = 0; i < 4; i++)
#pragma unroll
                for (int j = 0; j < 4; j++) {
                    MMA_BF16(acc[i][j], afh[i][0], afh[i][1], afh[i][2], afh[i][3], bfh[j][0], bfh[j][1]);
                    MMA_BF16(acc[i][j], afl[i][0], afl[i][1], afl[i][2], afl[i][3], bfh[j][0], bfh[j][1]);
                    MMA_BF16(acc[i][j], afh[i][0], afh[i][1], afh[i][2], afh[i][3], bfl[j][0], bfl[j][1]);
                }
        }
        if (t + 1 < ntile) {
            unsigned* ah_n = Ah + ((t + 1) & 1) * 128 * KP;
            unsigned* al_n = Al + ((t + 1) & 1) * 128 * KP;
            unsigned* bh_n = Bh + ((t + 1) & 1) * 128 * KP;
            unsigned* bl_n = Bl + ((t + 1) & 1) * 128 * KP;
#pragma unroll
            for (int p = 0; p < 4; p++) {
                int row = lrow + p * 32;
                unsigned h0, l0, h1, l1;
                splitbf(ra[p].x, ra[p].y, h0, l0);
                splitbf(ra[p].z, ra[p].w, h1, l1);
                ah_n[row * KP + kp0] = h0; ah_n[row * KP + kp0 + 1] = h1;
                al_n[row * KP + kp0] = l0; al_n[row * KP + kp0 + 1] = l1;
                splitbf(rb[p].x, rb[p].y, h0, l0);
                splitbf(rb[p].z, rb[p].w, h1, l1);
                bh_n[row * KP + kp0] = h0; bh_n[row * KP + kp0 + 1] = h1;
                bl_n[row * KP + kp0] = l0; bl_n[row * KP + kp0 + 1] = l1;
            }
        }
        __syncthreads();
    }

#pragma unroll
    for (int i = 0; i < 4; i++) {
        int row = m0 + wm * 64 + i * 16 + qr;
#pragma unroll
        for (int j = 0; j < 4; j++) {
            int col = n0 + wn * 32 + j * 8 + 2 * qc;
            *reinterpret_cast<float2*>(C + (size_t)row * N + col) =
                make_float2(acc[i][j][0], acc[i][j][1]);
            *reinterpret_cast<float2*>(C + (size_t)(row + 8) * N + col) =
                make_float2(acc[i][j][2], acc[i][j][3]);
        }
    }
}

// ---------------- per-head RMSNorm + RoPE + gain (q and k) ----------------
__global__ __launch_bounds__(128) void norm_rope_kernel(const float* __restrict__ gain) {
    int gw = (blockIdx.x * 128 + threadIdx.x) >> 5;
    int lane = threadIdx.x & 31;
    const int NQ = BB * TT * NH;
    const int NK = BB * TT * HKV;
    float* ptr;
    float g;
    int t;
    if (gw < NQ) {
        int h = gw % NH;
        int bt = gw / NH;
        t = bt % TT;
        ptr = g_qkv + (size_t)bt * NQKV + h * HD;
        g = gain[h];
    } else {
        int w2 = gw - NQ;
        if (w2 >= NK) return;
        int hk = w2 % HKV;
        int bt = w2 / HKV;
        t = bt % TT;
        ptr = g_qkv + (size_t)bt * NQKV + 1024 + hk * HD;
        g = 1.f;
    }
    float2 v = reinterpret_cast<const float2*>(ptr)[lane];
    float ss = v.x * v.x + v.y * v.y;
#pragma unroll
    for (int o = 16; o; o >>= 1) ss += __shfl_xor_sync(0xffffffffu, ss, o);
    float r = rsqrtf(ss * (1.f / 64.f) + 1.19209290e-07f);
    float n0 = v.x * r, n1 = v.y * r;
    float p0 = __shfl_xor_sync(0xffffffffu, n0, 8);
    float p1 = __shfl_xor_sync(0xffffffffu, n1, 8);
    float o0 = n0, o1 = n1;
    if (lane < 16) {
        int i0 = (2 * lane) & 15;
        float inv0 = powf(10000.f, -(float)i0 * (1.f / 16.f));
        float inv1 = powf(10000.f, -(float)(i0 + 1) * (1.f / 16.f));
        float a0 = (float)t * inv0, a1 = (float)t * inv1;
        float c0 = cosf(a0), s0 = sinf(a0);
        float c1 = cosf(a1), s1 = sinf(a1);
        if (lane < 8) {
            o0 = n0 * c0 + p0 * s0;
            o1 = n1 * c1 + p1 * s1;
        } else {
            o0 = -p0 * s0 + n0 * c0;
            o1 = -p1 * s1 + n1 * c1;
        }
    }
    reinterpret_cast<float2*>(ptr)[lane] = make_float2(o0 * g, o1 * g);
}

// ---------------- tensor-core causal flash attention (3x-bf16) -------------
// BM=128 (8 warps x m16), BN=64, D=64. Register-resident P, ldmatrix K frags,
// fused v-direction rejection in the epilogue.
#define KSTR 36
#define VSTR 72

__global__ void __launch_bounds__(256) attn_tc_kernel() {
    extern __shared__ unsigned smu[];
    unsigned* Khi = smu;                  // [64][KSTR]
    unsigned* Klo = smu + 64 * KSTR;
    unsigned* Vph = smu + 2 * 64 * KSTR;  // [32][VSTR]
    unsigned* Vpl = smu + 2 * 64 * KSTR + 32 * VSTR;

    const int b = blockIdx.z, h = blockIdx.y;
    const int qt = (gridDim.x - 1) - blockIdx.x;   // heavy blocks first
    const int hk = h >> 2;
    const int tid = threadIdx.x;
    const int lane = tid & 31;
    const int w = tid >> 5;
    const int qr = lane >> 2;
    const int qc = lane & 3;
    const int qbase = qt * 128 + w * 16;
    const int qi0 = qbase + qr, qi1 = qbase + qr + 8;

    // ldmatrix lane addressing for K fragments
    const int lt = lane >> 3, lr = lane & 7;
    const int baseK = lr * KSTR + (lt & 1) * 4 + (lt >> 1) * 8 * KSTR;

    // Q fragments (bf16 hi/lo packed pairs)
    unsigned qh[4][4], ql[4][4];
    {
        const float* Qp = g_qkv + ((size_t)b * TT + qbase) * NQKV + h * HD;
#pragma unroll
        for (int ks = 0; ks < 4; ks++) {
            int c0 = ks * 16 + 2 * qc;
            float2 x0 = *reinterpret_cast<const float2*>(Qp + (size_t)qr * NQKV + c0);
            float2 x1 = *reinterpret_cast<const float2*>(Qp + (size_t)(qr + 8) * NQKV + c0);
            float2 x2 = *reinterpret_cast<const float2*>(Qp + (size_t)qr * NQKV + c0 + 8);
            float2 x3 = *reinterpret_cast<const float2*>(Qp + (size_t)(qr + 8) * NQKV + c0 + 8);
            splitbf(x0.x, x0.y, qh[ks][0], ql[ks][0]);
            splitbf(x1.x, x1.y, qh[ks][1], ql[ks][1]);
            splitbf(x2.x, x2.y, qh[ks][2], ql[ks][2]);
            splitbf(x3.x, x3.y, qh[ks][3], ql[ks][3]);
        }
    }

    float yac[8][4] = {};
    float m0 = -1e30f, m1 = -1e30f, l0 = 0.f, l1 = 0.f;

    const int ktmax = 2 * qt + 1;
    for (int kt = 0; kt <= ktmax; kt++) {
        // ---- stage K tile ----
#pragma unroll
        for (int i = 0; i < 4; i++) {
            int it = tid + i * 256;
            int rr = it >> 4;
            int ddf = (it & 15) * 4;
            size_t base = ((size_t)b * TT + kt * 64 + rr) * NQKV + 1024 + hk * HD + ddf;
            float4 kv = *reinterpret_cast<const float4*>(g_qkv + base);
            unsigned h0, l0r, h1, l1r;
            splitbf(kv.x, kv.y, h0, l0r);
            splitbf(kv.z, kv.w, h1, l1r);
            int o = rr * KSTR + ddf / 2;
            Khi[o] = h0; Khi[o + 1] = h1;
            Klo[o] = l0r; Klo[o + 1] = l1r;
        }
        // ---- stage V tile (key-pair transposed) ----
#pragma unroll
        for (int i = 0; i < 2; i++) {
            int it = tid + i * 256;
            int r2 = it >> 4;
            int ddf = (it & 15) * 4;
            size_t base = ((size_t)b * TT + kt * 64 + 2 * r2) * NQKV + 1280 + hk * HD + ddf;
            float4 v0 = *reinterpret_cast<const float4*>(g_qkv + base);
            float4 v1 = *reinterpret_cast<const float4*>(g_qkv + base + NQKV);
            int o = r2 * VSTR + ddf;
            unsigned hh, ll;
            splitbf(v0.x, v1.x, hh, ll); Vph[o] = hh;     Vpl[o] = ll;
            splitbf(v0.y, v1.y, hh, ll); Vph[o + 1] = hh; Vpl[o + 1] = ll;
            splitbf(v0.z, v1.z, hh, ll); Vph[o + 2] = hh; Vpl[o + 2] = ll;
            splitbf(v0.w, v1.w, hh, ll); Vph[o + 3] = hh; Vpl[o + 3] = ll;
        }
        __syncthreads();

        if (kt * 64 <= qbase + 15) {
            // ---- S = Q K^T (3x bf16, K frags via ldmatrix) ----
            float sf[8][4] = {};
#pragma unroll
            for (int ks = 0; ks < 4; ks++) {
#pragma unroll
                for (int jp = 0; jp < 4; jp++) {
                    int o = baseK + (jp * 2) * 8 * KSTR + ks * 8;
                    unsigned kh[4], kl[4];
                    ldsm4(kh[0], kh[1], kh[2], kh[3], Khi + o);
                    ldsm4(kl[0], kl[1], kl[2], kl[3], Klo + o);
                    MMA_BF16(sf[2 * jp], qh[ks][0], qh[ks][1], qh[ks][2], qh[ks][3], kh[0], kh[1]);
                    MMA_BF16(sf[2 * jp], ql[ks][0], ql[ks][1], ql[ks][2], ql[ks][3], kh[0], kh[1]);
                    MMA_BF16(sf[2 * jp], qh[ks][0], qh[ks][1], qh[ks][2], qh[ks][3], kl[0], kl[1]);
                    MMA_BF16(sf[2 * jp + 1], qh[ks][0], qh[ks][1], qh[ks][2], qh[ks][3], kh[2], kh[3]);
                    MMA_BF16(sf[2 * jp + 1], ql[ks][0], ql[ks][1], ql[ks][2], ql[ks][3], kh[2], kh[3]);
                    MMA_BF16(sf[2 * jp + 1], qh[ks][0], qh[ks][1], qh[ks][2], qh[ks][3], kl[2], kl[3]);
                }
            }
            // ---- scale + causal mask ----
#pragma unroll
            for (int j = 0; j < 8; j++) {
                int kj = kt * 64 + j * 8 + 2 * qc;
                sf[j][0] = (kj     <= qi0) ? sf[j][0] * 0.125f : -1e30f;
                sf[j][1] = (kj + 1 <= qi0) ? sf[j][1] * 0.125f : -1e30f;
                sf[j][2] = (kj     <= qi1) ? sf[j][2] * 0.125f : -1e30f;
                sf[j][3] = (kj + 1 <= qi1) ? sf[j][3] * 0.125f : -1e30f;
            }
            // ---- online softmax ----
            float cm0 = -1e30f, cm1 = -1e30f;
#pragma unroll
            for (int j = 0; j < 8; j++) {
                cm0 = fmaxf(cm0, fmaxf(sf[j][0], sf[j][1]));
                cm1 = fmaxf(cm1, fmaxf(sf[j][2], sf[j][3]));
            }
            cm0 = fmaxf(cm0, __shfl_xor_sync(0xffffffffu, cm0, 1));
            cm0 = fmaxf(cm0, __shfl_xor_sync(0xffffffffu, cm0, 2));
            cm1 = fmaxf(cm1, __shfl_xor_sync(0xffffffffu, cm1, 1));
            cm1 = fmaxf(cm1, __shfl_xor_sync(0xffffffffu, cm1, 2));
            float mn0 = fmaxf(m0, cm0), mn1 = fmaxf(m1, cm1);
            float a0 = __expf(m0 - mn0), a1 = __expf(m1 - mn1);
#pragma unroll
            for (int jd = 0; jd < 8; jd++) {
                yac[jd][0] *= a0; yac[jd][1] *= a0;
                yac[jd][2] *= a1; yac[jd][3] *= a1;
            }
            unsigned ph0[8], ph1[8], pl0[8], pl1[8];
            float rs0 = 0.f, rs1 = 0.f;
#pragma unroll
            for (int j = 0; j < 8; j++) {
                float p0 = __expf(sf[j][0] - mn0);
                float p1 = __expf(sf[j][1] - mn0);
                float p2 = __expf(sf[j][2] - mn1);
                float p3 = __expf(sf[j][3] - mn1);
                rs0 += p0 + p1; rs1 += p2 + p3;
                splitbf(p0, p1, ph0[j], pl0[j]);
                splitbf(p2, p3, ph1[j], pl1[j]);
            }
            rs0 += __shfl_xor_sync(0xffffffffu, rs0, 1);
            rs0 += __shfl_xor_sync(0xffffffffu, rs0, 2);
            rs1 += __shfl_xor_sync(0xffffffffu, rs1, 1);
            rs1 += __shfl_xor_sync(0xffffffffu, rs1, 2);
            l0 = l0 * a0 + rs0;
            l1 = l1 * a1 + rs1;
            m0 = mn0; m1 = mn1;
            // ---- Y += P V (3x bf16), P from registers ----
#pragma unroll
            for (int ks = 0; ks < 4; ks++) {
                unsigned a0h = ph0[2 * ks], a1h = ph1[2 * ks];
                unsigned a2h = ph0[2 * ks + 1], a3h = ph1[2 * ks + 1];
                unsigned a0l = pl0[2 * ks], a1l = pl1[2 * ks];
                unsigned a2l = pl0[2 * ks + 1], a3l = pl1[2 * ks + 1];
#pragma unroll
                for (int jd = 0; jd < 8; jd++) {
                    int vb = (ks * 8 + qc) * VSTR + jd * 8 + qr;
                    unsigned vh0 = Vph[vb], vh1 = Vph[vb + 4 * VSTR];
                    unsigned vl0 = Vpl[vb], vl1 = Vpl[vb + 4 * VSTR];
                    MMA_BF16(yac[jd], a0h, a1h, a2h, a3h, vh0, vh1);
                    MMA_BF16(yac[jd], a0l, a1l, a2l, a3l, vh0, vh1);
                    MMA_BF16(yac[jd], a0h, a1h, a2h, a3h, vl0, vl1);
                }
            }
        }
        __syncthreads();
    }

    // ---- epilogue: normalize + fused v-direction rejection ----
    float inv0 = 1.f / l0, inv1 = 1.f / l1;
    float2 y0[8], y1[8], v0[8], v1[8];
    {
        const float* Vq0 = g_qkv + ((size_t)b * TT + qi0) * NQKV + 1280 + hk * HD;
        const float* Vq1 = g_qkv + ((size_t)b * TT + qi1) * NQKV + 1280 + hk * HD;
#pragma unroll
        for (int jd = 0; jd < 8; jd++) {
            int col = jd * 8 + 2 * qc;
            y0[jd] = make_float2(yac[jd][0] * inv0, yac[jd][1] * inv0);
            y1[jd] = make_float2(yac[jd][2] * inv1, yac[jd][3] * inv1);
            v0[jd] = *reinterpret_cast<const float2*>(Vq0 + col);
            v1[jd] = *reinterpret_cast<const float2*>(Vq1 + col);
        }
    }
    float ns0 = 0.f, ns1 = 0.f, dt0 = 0.f, dt1 = 0.f;
#pragma unroll
    for (int jd = 0; jd < 8; jd++) {
        ns0 += v0[jd].x * v0[jd].x + v0[jd].y * v0[jd].y;
        ns1 += v1[jd].x * v1[jd].x + v1[jd].y * v1[jd].y;
        dt0 += y0[jd].x * v0[jd].x + y0[jd].y * v0[jd].y;
        dt1 += y1[jd].x * v1[jd].x + y1[jd].y * v1[jd].y;
    }
    ns0 += __shfl_xor_sync(0xffffffffu, ns0, 1); ns0 += __shfl_xor_sync(0xffffffffu, ns0, 2);
    ns1 += __shfl_xor_sync(0xffffffffu, ns1, 1); ns1 += __shfl_xor_sync(0xffffffffu, ns1, 2);
    dt0 += __shfl_xor_sync(0xffffffffu, dt0, 1); dt0 += __shfl_xor_sync(0xffffffffu, dt0, 2);
    dt1 += __shfl_xor_sync(0xffffffffu, dt1, 1); dt1 += __shfl_xor_sync(0xffffffffu, dt1, 2);
    float in0 = 1.f / fmaxf(sqrtf(ns0), 1e-12f);
    float in1 = 1.f / fmaxf(sqrtf(ns1), 1e-12f);
    float c0 = dt0 * in0 * in0, c1 = dt1 * in1 * in1;   // (y.vn)/||v|| applied to raw v

    float* Yp0 = g_yo + ((size_t)b * TT + qi0) * DIM + h * HD;
    float* Yp1 = g_yo + ((size_t)b * TT + qi1) * DIM + h * HD;
#pragma unroll
    for (int jd = 0; jd < 8; jd++) {
        int col = jd * 8 + 2 * qc;
        *reinterpret_cast<float2*>(Yp0 + col) =
            make_float2(y0[jd].x - c0 * v0[jd].x, y0[jd].y - c0 * v0[jd].y);
        *reinterpret_cast<float2*>(Yp1 + col) =
            make_float2(y1[jd].x - c1 * v1[jd].x, y1[jd].y - c1 * v1[jd].y);
    }
}

// ---------------- launch ----------------
extern "C" void kernel_launch(void* const* d_in, const int* in_sizes, int n_in,
                              void* d_out, int out_size) {
    const float* x      = (const float*)d_in[0];
    const float* w_q    = (const float*)d_in[1];
    const float* w_k    = (const float*)d_in[2];
    const float* w_v    = (const float*)d_in[3];
    const float* w_proj = (const float*)d_in[4];
    const float* q_gain = (const float*)d_in[5];

    float *w, *wp, *qkv, *yo;
    cudaGetSymbolAddress((void**)&w, g_w);
    cudaGetSymbolAddress((void**)&wp, g_wp);
    cudaGetSymbolAddress((void**)&qkv, g_qkv);
    cudaGetSymbolAddress((void**)&yo, g_yo);

    const int M = BB * TT;          // 4096
    const int SMEM = 8 * 128 * KP * sizeof(unsigned);                     // 81920
    const int ASMEM = (2 * 64 * KSTR + 2 * 32 * VSTR) * sizeof(unsigned); // 36864

    static bool attr_set = false;
    if (!attr_set) {
        cudaFuncSetAttribute(bf16_gemm_nt, cudaFuncAttributeMaxDynamicSharedMemorySize, SMEM);
        cudaFuncSetAttribute(attn_tc_kernel, cudaFuncAttributeMaxDynamicSharedMemorySize, ASMEM);
        attr_set = true;
    }

    // fake-quant weights (fused qkv buffer + separate proj)
    quant_fused_kernel<<<NQKV, 256>>>(w_q, w_k, w_v, w);
    quant_kernel<<<DIM, 256>>>(w_proj, wp, 16.f);

    // fused QKV projection: [4096 x 1536] = x @ W^T
    bf16_gemm_nt<<<dim3(NQKV / 128, M / 128), 256, SMEM>>>(x, w, qkv, M, NQKV, DIM);

    // RMSNorm + RoPE + gain on q and k
    {
        int warps = BB * TT * (NH + HKV);
        norm_rope_kernel<<<warps / 4, 128>>>(q_gain);
    }

    // causal attention + fused v-rejection
    attn_tc_kernel<<<dim3(TT / 128, NH, BB), 256, ASMEM>>>();

    // output projection
    bf16_gemm_nt<<<dim3(DIM / 128, M / 128), 256, SMEM>>>(yo, wp, (float*)d_out, M, DIM, DIM);
}

// round 10
// speedup vs baseline: 4.5374x; 1.1497x over previous
#include <cuda_runtime.h>
#include <cuda_bf16.h>
#include <math.h>

#define BB 2
#define TT 2048
#define DIM 1024
#define NH 16
#define HKV 4
#define HD 64
#define NQKV 1536   // 1024 q + 256 k + 256 v

// ---------------- scratch (device globals, no allocation) ----------------
__device__ __nv_bfloat16 g_wbf[NQKV * DIM];   // quantized qkv weights as exact bf16 ints
__device__ float g_wsc[NQKV];                 // per-row scales
__device__ __nv_bfloat16 g_wpbf[DIM * DIM];   // quantized proj weights
__device__ float g_wpsc[DIM];
__device__ float g_qkv[BB * TT * NQKV];       // fused q|k|v activations per token
__device__ float g_yo[BB * TT * DIM];

// exact 10000^(-j/16) = 10^(-j/4)
__device__ __constant__ float c_invfreq[16] = {
    1.0f, 0.5623413252f, 0.3162277660f, 0.1778279410f,
    0.1f, 0.05623413252f, 0.03162277660f, 0.01778279410f,
    0.01f, 5.623413252e-3f, 3.162277660e-3f, 1.778279410e-3f,
    1e-3f, 5.623413252e-4f, 3.162277660e-4f, 1.778279410e-4f};

// ---------------- bf16 split helpers ----------------
__device__ __forceinline__ void splitbf(float x, float y, unsigned& hi, unsigned& lo) {
    __nv_bfloat162 h = __floats2bfloat162_rn(x, y);
    float hx = __low2float(h), hy = __high2float(h);
    __nv_bfloat162 l = __floats2bfloat162_rn(x - hx, y - hy);
    hi = *reinterpret_cast<unsigned*>(&h);
    lo = *reinterpret_cast<unsigned*>(&l);
}

#define MMA_BF16(C, A0, A1, A2, A3, B0, B1)                                   \
    asm volatile(                                                             \
        "mma.sync.aligned.m16n8k16.row.col.f32.bf16.bf16.f32 "                \
        "{%0,%1,%2,%3}, {%4,%5,%6,%7}, {%8,%9}, {%0,%1,%2,%3};\n"             \
        : "+f"(C[0]), "+f"(C[1]), "+f"(C[2]), "+f"(C[3])                      \
        : "r"(A0), "r"(A1), "r"(A2), "r"(A3), "r"(B0), "r"(B1))

__device__ __forceinline__ void ldsm4(unsigned& r0, unsigned& r1, unsigned& r2, unsigned& r3,
                                      const unsigned* p) {
    unsigned addr = (unsigned)__cvta_generic_to_shared(p);
    asm volatile("ldmatrix.sync.aligned.m8n8.x4.shared.b16 {%0,%1,%2,%3}, [%4];"
                 : "=r"(r0), "=r"(r1), "=r"(r2), "=r"(r3) : "r"(addr));
}

// ---------------- fake_quant: all weight rows in one launch ----------------
__global__ __launch_bounds__(256) void quant_all_kernel(const float* __restrict__ wq,
                                                        const float* __restrict__ wk,
                                                        const float* __restrict__ wv,
                                                        const float* __restrict__ wp) {
    __shared__ float red[256];
    int r = blockIdx.x;
    const float* src;
    float halfv;
    __nv_bfloat16* dst;
    float* scd;
    int dr;
    if (r < 1024)      { src = wq + (size_t)r * DIM;          halfv = 32.f; dst = g_wbf;  scd = g_wsc;  dr = r; }
    else if (r < 1280) { src = wk + (size_t)(r - 1024) * DIM; halfv = 32.f; dst = g_wbf;  scd = g_wsc;  dr = r; }
    else if (r < 1536) { src = wv + (size_t)(r - 1280) * DIM; halfv = 16.f; dst = g_wbf;  scd = g_wsc;  dr = r; }
    else               { src = wp + (size_t)(r - 1536) * DIM; halfv = 16.f; dst = g_wpbf; scd = g_wpsc; dr = r - 1536; }

    float m = 0.f;
    for (int c = threadIdx.x; c < DIM; c += 256) m = fmaxf(m, fabsf(src[c]));
    red[threadIdx.x] = m;
    __syncthreads();
    for (int s = 128; s > 0; s >>= 1) {
        if (threadIdx.x < s) red[threadIdx.x] = fmaxf(red[threadIdx.x], red[threadIdx.x + s]);
        __syncthreads();
    }
    float wmax = fmaxf(red[0], 1e-5f);
    float sc = halfv / wmax, isc = wmax / halfv;
    for (int c = threadIdx.x; c < DIM; c += 256) {
        float q = rintf(src[c] * sc);
        q = fminf(fmaxf(q, -halfv), halfv - 1.f);
        dst[(size_t)dr * DIM + c] = __float2bfloat16(q);   // exact integer
    }
    if (threadIdx.x == 0) scd[dr] = isc;
}

// ---------------- 2x-bf16 GEMM: C[M,N] = (A @ Qbf^T) * diag(scale) ---------
// A fp32 split hi/lo (2 MMA terms); B exact bf16 (direct copy to smem).
#define KP 20

__global__ void __launch_bounds__(256) bf16_gemm_wq(const float* __restrict__ A,
                                                    const __nv_bfloat16* __restrict__ B,
                                                    const float* __restrict__ bsc,
                                                    float* __restrict__ C,
                                                    int M, int N, int K) {
    extern __shared__ unsigned smu[];
    unsigned* Ah = smu;                   // [2][128][KP]
    unsigned* Al = smu + 2 * 128 * KP;
    unsigned* Bh = smu + 4 * 128 * KP;    // [2][128][KP]

    const int tid = threadIdx.x;
    const int lane = tid & 31;
    const int wid = tid >> 5;
    const int wm = wid & 1;
    const int wn = wid >> 1;
    const int qr = lane >> 2;
    const int qc = lane & 3;
    const int m0 = blockIdx.y * 128, n0 = blockIdx.x * 128;
    const int lrow = tid >> 3;
    const int lkf = (tid & 7) * 4;
    const int kp0 = (tid & 7) * 2;
    const int brow = tid >> 1;
    const int bq = (tid & 1) * 2;

    // ldmatrix lane addressing
    const int lt = lane >> 3, lr = lane & 7;
    const int baseA = (wm * 64 + lr + (lt & 1) * 8) * KP + (lt >> 1) * 4;
    const int baseB = (wn * 32 + lr) * KP + (lt & 1) * 4;
    const int jrowB = (lt >> 1) * 8 * KP;

    float acc[4][4][4] = {};
    float4 ra[4];
    uint4 rbv[2];
    const int ntile = K / 32;

    // prefetch tile 0
#pragma unroll
    for (int p = 0; p < 4; p++)
        ra[p] = *reinterpret_cast<const float4*>(A + (size_t)(m0 + lrow + p * 32) * K + lkf);
    {
        const uint4* bp = reinterpret_cast<const uint4*>(B + (size_t)(n0 + brow) * K);
        rbv[0] = bp[bq]; rbv[1] = bp[bq + 1];
    }
    // stage tile 0
#pragma unroll
    for (int p = 0; p < 4; p++) {
        int row = lrow + p * 32;
        unsigned h0, l0, h1, l1;
        splitbf(ra[p].x, ra[p].y, h0, l0);
        splitbf(ra[p].z, ra[p].w, h1, l1);
        Ah[row * KP + kp0] = h0; Ah[row * KP + kp0 + 1] = h1;
        Al[row * KP + kp0] = l0; Al[row * KP + kp0 + 1] = l1;
    }
    *reinterpret_cast<uint4*>(Bh + brow * KP + bq * 4) = rbv[0];
    *reinterpret_cast<uint4*>(Bh + brow * KP + bq * 4 + 4) = rbv[1];
    __syncthreads();

    for (int t = 0; t < ntile; t++) {
        if (t + 1 < ntile) {
            int koff = (t + 1) * 32;
#pragma unroll
            for (int p = 0; p < 4; p++)
                ra[p] = *reinterpret_cast<const float4*>(A + (size_t)(m0 + lrow + p * 32) * K + koff + lkf);
            const uint4* bp = reinterpret_cast<const uint4*>(B + (size_t)(n0 + brow) * K + koff);
            rbv[0] = bp[bq]; rbv[1] = bp[bq + 1];
        }
        const unsigned* ah_b = Ah + (t & 1) * 128 * KP;
        const unsigned* al_b = Al + (t & 1) * 128 * KP;
        const unsigned* bh_b = Bh + (t & 1) * 128 * KP;
#pragma unroll
        for (int ks = 0; ks < 2; ks++) {
            unsigned afh[4][4], afl[4][4], bfh[4][2];
#pragma unroll
            for (int i = 0; i < 4; i++) {
                int o = baseA + i * 16 * KP + ks * 8;
                ldsm4(afh[i][0], afh[i][1], afh[i][2], afh[i][3], ah_b + o);
                ldsm4(afl[i][0], afl[i][1], afl[i][2], afl[i][3], al_b + o);
            }
#pragma unroll
            for (int jp = 0; jp < 2; jp++) {
                int o = baseB + (jp * 2) * 8 * KP + jrowB + ks * 8;
                ldsm4(bfh[2 * jp][0], bfh[2 * jp][1], bfh[2 * jp + 1][0], bfh[2 * jp + 1][1], bh_b + o);
            }
#pragma unroll
            for (int i = 0; i < 4; i++)
#pragma unroll
                for (int j = 0; j < 4; j++) {
                    MMA_BF16(acc[i][j], afh[i][0], afh[i][1], afh[i][2], afh[i][3], bfh[j][0], bfh[j][1]);
                    MMA_BF16(acc[i][j], afl[i][0], afl[i][1], afl[i][2], afl[i][3], bfh[j][0], bfh[j][1]);
                }
        }
        if (t + 1 < ntile) {
            unsigned* ah_n = Ah + ((t + 1) & 1) * 128 * KP;
            unsigned* al_n = Al + ((t + 1) & 1) * 128 * KP;
            unsigned* bh_n = Bh + ((t + 1) & 1) * 128 * KP;
#pragma unroll
            for (int p = 0; p < 4; p++) {
                int row = lrow + p * 32;
                unsigned h0, l0, h1, l1;
                splitbf(ra[p].x, ra[p].y, h0, l0);
                splitbf(ra[p].z, ra[p].w, h1, l1);
                ah_n[row * KP + kp0] = h0; ah_n[row * KP + kp0 + 1] = h1;
                al_n[row * KP + kp0] = l0; al_n[row * KP + kp0 + 1] = l1;
            }
            *reinterpret_cast<uint4*>(bh_n + brow * KP + bq * 4) = rbv[0];
            *reinterpret_cast<uint4*>(bh_n + brow * KP + bq * 4 + 4) = rbv[1];
        }
        __syncthreads();
    }

    // epilogue: per-column scale
#pragma unroll
    for (int i = 0; i < 4; i++) {
        int row = m0 + wm * 64 + i * 16 + qr;
#pragma unroll
        for (int j = 0; j < 4; j++) {
            int col = n0 + wn * 32 + j * 8 + 2 * qc;
            float2 s = *reinterpret_cast<const float2*>(bsc + col);
            *reinterpret_cast<float2*>(C + (size_t)row * N + col) =
                make_float2(acc[i][j][0] * s.x, acc[i][j][1] * s.y);
            *reinterpret_cast<float2*>(C + (size_t)(row + 8) * N + col) =
                make_float2(acc[i][j][2] * s.x, acc[i][j][3] * s.y);
        }
    }
}

// ---------------- per-head RMSNorm + RoPE + gain (q and k) ----------------
__global__ __launch_bounds__(128) void norm_rope_kernel(const float* __restrict__ gain) {
    int gw = (blockIdx.x * 128 + threadIdx.x) >> 5;
    int lane = threadIdx.x & 31;
    const int NQ = BB * TT * NH;
    const int NK = BB * TT * HKV;
    float* ptr;
    float g;
    int t;
    if (gw < NQ) {
        int h = gw % NH;
        int bt = gw / NH;
        t = bt % TT;
        ptr = g_qkv + (size_t)bt * NQKV + h * HD;
        g = gain[h];
    } else {
        int w2 = gw - NQ;
        if (w2 >= NK) return;
        int hk = w2 % HKV;
        int bt = w2 / HKV;
        t = bt % TT;
        ptr = g_qkv + (size_t)bt * NQKV + 1024 + hk * HD;
        g = 1.f;
    }
    float2 v = reinterpret_cast<const float2*>(ptr)[lane];
    float ss = v.x * v.x + v.y * v.y;
#pragma unroll
    for (int o = 16; o; o >>= 1) ss += __shfl_xor_sync(0xffffffffu, ss, o);
    float r = rsqrtf(ss * (1.f / 64.f) + 1.19209290e-07f);
    float n0 = v.x * r, n1 = v.y * r;
    float p0 = __shfl_xor_sync(0xffffffffu, n0, 8);
    float p1 = __shfl_xor_sync(0xffffffffu, n1, 8);
    float o0 = n0, o1 = n1;
    if (lane < 16) {
        int i0 = (2 * lane) & 15;
        float a0 = (float)t * c_invfreq[i0];
        float a1 = (float)t * c_invfreq[(i0 + 1) & 15];
        if (i0 == 15) a1 = 0.f;   // unreachable (i0 even), keep compiler honest
        float c0, s0, c1, s1;
        sincosf(a0, &s0, &c0);
        sincosf(a1, &s1, &c1);
        if (lane < 8) {
            o0 = n0 * c0 + p0 * s0;
            o1 = n1 * c1 + p1 * s1;
        } else {
            o0 = -p0 * s0 + n0 * c0;
            o1 = -p1 * s1 + n1 * c1;
        }
    }
    reinterpret_cast<float2*>(ptr)[lane] = make_float2(o0 * g, o1 * g);
}

// ---------------- tensor-core causal flash attention (3x-bf16) -------------
#define KSTR 36
#define VSTR 72

__global__ void __launch_bounds__(256) attn_tc_kernel() {
    extern __shared__ unsigned smu[];
    unsigned* Khi = smu;                  // [64][KSTR]
    unsigned* Klo = smu + 64 * KSTR;
    unsigned* Vph = smu + 2 * 64 * KSTR;  // [32][VSTR]
    unsigned* Vpl = smu + 2 * 64 * KSTR + 32 * VSTR;

    const int b = blockIdx.z, h = blockIdx.y;
    const int qt = (gridDim.x - 1) - blockIdx.x;   // heavy blocks first
    const int hk = h >> 2;
    const int tid = threadIdx.x;
    const int lane = tid & 31;
    const int w = tid >> 5;
    const int qr = lane >> 2;
    const int qc = lane & 3;
    const int qbase = qt * 128 + w * 16;
    const int qi0 = qbase + qr, qi1 = qbase + qr + 8;

    const int lt = lane >> 3, lr = lane & 7;
    const int baseK = lr * KSTR + (lt & 1) * 4 + (lt >> 1) * 8 * KSTR;

    unsigned qh[4][4], ql[4][4];
    {
        const float* Qp = g_qkv + ((size_t)b * TT + qbase) * NQKV + h * HD;
#pragma unroll
        for (int ks = 0; ks < 4; ks++) {
            int c0 = ks * 16 + 2 * qc;
            float2 x0 = *reinterpret_cast<const float2*>(Qp + (size_t)qr * NQKV + c0);
            float2 x1 = *reinterpret_cast<const float2*>(Qp + (size_t)(qr + 8) * NQKV + c0);
            float2 x2 = *reinterpret_cast<const float2*>(Qp + (size_t)qr * NQKV + c0 + 8);
            float2 x3 = *reinterpret_cast<const float2*>(Qp + (size_t)(qr + 8) * NQKV + c0 + 8);
            splitbf(x0.x, x0.y, qh[ks][0], ql[ks][0]);
            splitbf(x1.x, x1.y, qh[ks][1], ql[ks][1]);
            splitbf(x2.x, x2.y, qh[ks][2], ql[ks][2]);
            splitbf(x3.x, x3.y, qh[ks][3], ql[ks][3]);
        }
    }

    float yac[8][4] = {};
    float m0 = -1e30f, m1 = -1e30f, l0 = 0.f, l1 = 0.f;

    const int ktmax = 2 * qt + 1;
    for (int kt = 0; kt <= ktmax; kt++) {
#pragma unroll
        for (int i = 0; i < 4; i++) {
            int it = tid + i * 256;
            int rr = it >> 4;
            int ddf = (it & 15) * 4;
            size_t base = ((size_t)b * TT + kt * 64 + rr) * NQKV + 1024 + hk * HD + ddf;
            float4 kv = *reinterpret_cast<const float4*>(g_qkv + base);
            unsigned h0, l0r, h1, l1r;
            splitbf(kv.x, kv.y, h0, l0r);
            splitbf(kv.z, kv.w, h1, l1r);
            int o = rr * KSTR + ddf / 2;
            Khi[o] = h0; Khi[o + 1] = h1;
            Klo[o] = l0r; Klo[o + 1] = l1r;
        }
#pragma unroll
        for (int i = 0; i < 2; i++) {
            int it = tid + i * 256;
            int r2 = it >> 4;
            int ddf = (it & 15) * 4;
            size_t base = ((size_t)b * TT + kt * 64 + 2 * r2) * NQKV + 1280 + hk * HD + ddf;
            float4 v0 = *reinterpret_cast<const float4*>(g_qkv + base);
            float4 v1 = *reinterpret_cast<const float4*>(g_qkv + base + NQKV);
            int o = r2 * VSTR + ddf;
            unsigned hh, ll;
            splitbf(v0.x, v1.x, hh, ll); Vph[o] = hh;     Vpl[o] = ll;
            splitbf(v0.y, v1.y, hh, ll); Vph[o + 1] = hh; Vpl[o + 1] = ll;
            splitbf(v0.z, v1.z, hh, ll); Vph[o + 2] = hh; Vpl[o + 2] = ll;
            splitbf(v0.w, v1.w, hh, ll); Vph[o + 3] = hh; Vpl[o + 3] = ll;
        }
        __syncthreads();

        if (kt * 64 <= qbase + 15) {
            float sf[8][4] = {};
#pragma unroll
            for (int ks = 0; ks < 4; ks++) {
#pragma unroll
                for (int jp = 0; jp < 4; jp++) {
                    int o = baseK + (jp * 2) * 8 * KSTR + ks * 8;
                    unsigned kh[4], kl[4];
                    ldsm4(kh[0], kh[1], kh[2], kh[3], Khi + o);
                    ldsm4(kl[0], kl[1], kl[2], kl[3], Klo + o);
                    MMA_BF16(sf[2 * jp], qh[ks][0], qh[ks][1], qh[ks][2], qh[ks][3], kh[0], kh[1]);
                    MMA_BF16(sf[2 * jp], ql[ks][0], ql[ks][1], ql[ks][2], ql[ks][3], kh[0], kh[1]);
                    MMA_BF16(sf[2 * jp], qh[ks][0], qh[ks][1], qh[ks][2], qh[ks][3], kl[0], kl[1]);
                    MMA_BF16(sf[2 * jp + 1], qh[ks][0], qh[ks][1], qh[ks][2], qh[ks][3], kh[2], kh[3]);
                    MMA_BF16(sf[2 * jp + 1], ql[ks][0], ql[ks][1], ql[ks][2], ql[ks][3], kh[2], kh[3]);
                    MMA_BF16(sf[2 * jp + 1], qh[ks][0], qh[ks][1], qh[ks][2], qh[ks][3], kl[2], kl[3]);
                }
            }
#pragma unroll
            for (int j = 0; j < 8; j++) {
                int kj = kt * 64 + j * 8 + 2 * qc;
                sf[j][0] = (kj     <= qi0) ? sf[j][0] * 0.125f : -1e30f;
                sf[j][1] = (kj + 1 <= qi0) ? sf[j][1] * 0.125f : -1e30f;
                sf[j][2] = (kj     <= qi1) ? sf[j][2] * 0.125f : -1e30f;
                sf[j][3] = (kj + 1 <= qi1) ? sf[j][3] * 0.125f : -1e30f;
            }
            float cm0 = -1e30f, cm1 = -1e30f;
#pragma unroll
            for (int j = 0; j < 8; j++) {
                cm0 = fmaxf(cm0, fmaxf(sf[j][0], sf[j][1]));
                cm1 = fmaxf(cm1, fmaxf(sf[j][2], sf[j][3]));
            }
            cm0 = fmaxf(cm0, __shfl_xor_sync(0xffffffffu, cm0, 1));
            cm0 = fmaxf(cm0, __shfl_xor_sync(0xffffffffu, cm0, 2));
            cm1 = fmaxf(cm1, __shfl_xor_sync(0xffffffffu, cm1, 1));
            cm1 = fmaxf(cm1, __shfl_xor_sync(0xffffffffu, cm1, 2));
            float mn0 = fmaxf(m0, cm0), mn1 = fmaxf(m1, cm1);
            float a0 = __expf(m0 - mn0), a1 = __expf(m1 - mn1);
#pragma unroll
            for (int jd = 0; jd < 8; jd++) {
                yac[jd][0] *= a0; yac[jd][1] *= a0;
                yac[jd][2] *= a1; yac[jd][3] *= a1;
            }
            unsigned ph0[8], ph1[8], pl0[8], pl1[8];
            float rs0 = 0.f, rs1 = 0.f;
#pragma unroll
            for (int j = 0; j < 8; j++) {
                float p0 = __expf(sf[j][0] - mn0);
                float p1 = __expf(sf[j][1] - mn0);
                float p2 = __expf(sf[j][2] - mn1);
                float p3 = __expf(sf[j][3] - mn1);
                rs0 += p0 + p1; rs1 += p2 + p3;
                splitbf(p0, p1, ph0[j], pl0[j]);
                splitbf(p2, p3, ph1[j], pl1[j]);
            }
            rs0 += __shfl_xor_sync(0xffffffffu, rs0, 1);
            rs0 += __shfl_xor_sync(0xffffffffu, rs0, 2);
            rs1 += __shfl_xor_sync(0xffffffffu, rs1, 1);
            rs1 += __shfl_xor_sync(0xffffffffu, rs1, 2);
            l0 = l0 * a0 + rs0;
            l1 = l1 * a1 + rs1;
            m0 = mn0; m1 = mn1;
#pragma unroll
            for (int ks = 0; ks < 4; ks++) {
                unsigned a0h = ph0[2 * ks], a1h = ph1[2 * ks];
                unsigned a2h = ph0[2 * ks + 1], a3h = ph1[2 * ks + 1];
                unsigned a0l = pl0[2 * ks], a1l = pl1[2 * ks];
                unsigned a2l = pl0[2 * ks + 1], a3l = pl1[2 * ks + 1];
#pragma unroll
                for (int jd = 0; jd < 8; jd++) {
                    int vb = (ks * 8 + qc) * VSTR + jd * 8 + qr;
                    unsigned vh0 = Vph[vb], vh1 = Vph[vb + 4 * VSTR];
                    unsigned vl0 = Vpl[vb], vl1 = Vpl[vb + 4 * VSTR];
                    MMA_BF16(yac[jd], a0h, a1h, a2h, a3h, vh0, vh1);
                    MMA_BF16(yac[jd], a0l, a1l, a2l, a3l, vh0, vh1);
                    MMA_BF16(yac[jd], a0h, a1h, a2h, a3h, vl0, vl1);
                }
            }
        }
        __syncthreads();
    }

    // epilogue: normalize + fused v-direction rejection
    float inv0 = 1.f / l0, inv1 = 1.f / l1;
    float2 y0[8], y1[8], v0[8], v1[8];
    {
        const float* Vq0 = g_qkv + ((size_t)b * TT + qi0) * NQKV + 1280 + hk * HD;
        const float* Vq1 = g_qkv + ((size_t)b * TT + qi1) * NQKV + 1280 + hk * HD;
#pragma unroll
        for (int jd = 0; jd < 8; jd++) {
            int col = jd * 8 + 2 * qc;
            y0[jd] = make_float2(yac[jd][0] * inv0, yac[jd][1] * inv0);
            y1[jd] = make_float2(yac[jd][2] * inv1, yac[jd][3] * inv1);
            v0[jd] = *reinterpret_cast<const float2*>(Vq0 + col);
            v1[jd] = *reinterpret_cast<const float2*>(Vq1 + col);
        }
    }
    float ns0 = 0.f, ns1 = 0.f, dt0 = 0.f, dt1 = 0.f;
#pragma unroll
    for (int jd = 0; jd < 8; jd++) {
        ns0 += v0[jd].x * v0[jd].x + v0[jd].y * v0[jd].y;
        ns1 += v1[jd].x * v1[jd].x + v1[jd].y * v1[jd].y;
        dt0 += y0[jd].x * v0[jd].x + y0[jd].y * v0[jd].y;
        dt1 += y1[jd].x * v1[jd].x + y1[jd].y * v1[jd].y;
    }
    ns0 += __shfl_xor_sync(0xffffffffu, ns0, 1); ns0 += __shfl_xor_sync(0xffffffffu, ns0, 2);
    ns1 += __shfl_xor_sync(0xffffffffu, ns1, 1); ns1 += __shfl_xor_sync(0xffffffffu, ns1, 2);
    dt0 += __shfl_xor_sync(0xffffffffu, dt0, 1); dt0 += __shfl_xor_sync(0xffffffffu, dt0, 2);
    dt1 += __shfl_xor_sync(0xffffffffu, dt1, 1); dt1 += __shfl_xor_sync(0xffffffffu, dt1, 2);
    float in0 = 1.f / fmaxf(sqrtf(ns0), 1e-12f);
    float in1 = 1.f / fmaxf(sqrtf(ns1), 1e-12f);
    float c0 = dt0 * in0 * in0, c1 = dt1 * in1 * in1;

    float* Yp0 = g_yo + ((size_t)b * TT + qi0) * DIM + h * HD;
    float* Yp1 = g_yo + ((size_t)b * TT + qi1) * DIM + h * HD;
#pragma unroll
    for (int jd = 0; jd < 8; jd++) {
        int col = jd * 8 + 2 * qc;
        *reinterpret_cast<float2*>(Yp0 + col) =
            make_float2(y0[jd].x - c0 * v0[jd].x, y0[jd].y - c0 * v0[jd].y);
        *reinterpret_cast<float2*>(Yp1 + col) =
            make_float2(y1[jd].x - c1 * v1[jd].x, y1[jd].y - c1 * v1[jd].y);
    }
}

// ---------------- launch ----------------
extern "C" void kernel_launch(void* const* d_in, const int* in_sizes, int n_in,
                              void* d_out, int out_size) {
    const float* x      = (const float*)d_in[0];
    const float* w_q    = (const float*)d_in[1];
    const float* w_k    = (const float*)d_in[2];
    const float* w_v    = (const float*)d_in[3];
    const float* w_proj = (const float*)d_in[4];
    const float* q_gain = (const float*)d_in[5];

    __nv_bfloat16 *wbf, *wpbf;
    float *wsc, *wpsc, *qkv, *yo;
    cudaGetSymbolAddress((void**)&wbf, g_wbf);
    cudaGetSymbolAddress((void**)&wsc, g_wsc);
    cudaGetSymbolAddress((void**)&wpbf, g_wpbf);
    cudaGetSymbolAddress((void**)&wpsc, g_wpsc);
    cudaGetSymbolAddress((void**)&qkv, g_qkv);
    cudaGetSymbolAddress((void**)&yo, g_yo);

    const int M = BB * TT;          // 4096
    const int SMEM = 6 * 128 * KP * sizeof(unsigned);                     // 61440
    const int ASMEM = (2 * 64 * KSTR + 2 * 32 * VSTR) * sizeof(unsigned); // 36864

    static bool attr_set = false;
    if (!attr_set) {
        cudaFuncSetAttribute(bf16_gemm_wq, cudaFuncAttributeMaxDynamicSharedMemorySize, SMEM);
        cudaFuncSetAttribute(attn_tc_kernel, cudaFuncAttributeMaxDynamicSharedMemorySize, ASMEM);
        attr_set = true;
    }

    // fake-quant all weights (bf16 ints + per-row scales)
    quant_all_kernel<<<NQKV + DIM, 256>>>(w_q, w_k, w_v, w_proj);

    // fused QKV projection: [4096 x 1536]
    bf16_gemm_wq<<<dim3(NQKV / 128, M / 128), 256, SMEM>>>(x, wbf, wsc, qkv, M, NQKV, DIM);

    // RMSNorm + RoPE + gain
    {
        int warps = BB * TT * (NH + HKV);
        norm_rope_kernel<<<warps / 4, 128>>>(q_gain);
    }

    // causal attention + fused v-rejection
    attn_tc_kernel<<<dim3(TT / 128, NH, BB), 256, ASMEM>>>();

    // output projection
    bf16_gemm_wq<<<dim3(DIM / 128, M / 128), 256, SMEM>>>(yo, wpbf, wpsc, (float*)d_out, M, DIM, DIM);
}